// round 4
// baseline (speedup 1.0000x reference)
#include <cuda_runtime.h>
#include <cuda_bf16.h>
#include <math.h>
#include <stdint.h>

#define NTOK 4096
#define DMODEL 1024
#define NH 16
#define TSEQ 1024

// ---------------- helpers ----------------
__device__ __forceinline__ uint32_t smem_u32(const void* p) {
    uint32_t a;
    asm("{ .reg .u64 t; cvta.to.shared.u64 t, %1; cvt.u32.u64 %0, t; }" : "=r"(a) : "l"(p));
    return a;
}

#define LDSM4(r, addr) \
    asm volatile("ldmatrix.sync.aligned.m8n8.x4.shared.b16 {%0,%1,%2,%3}, [%4];" \
        : "=r"((r)[0]), "=r"((r)[1]), "=r"((r)[2]), "=r"((r)[3]) : "r"(addr))

#define LDSM4T(r, addr) \
    asm volatile("ldmatrix.sync.aligned.m8n8.x4.trans.shared.b16 {%0,%1,%2,%3}, [%4];" \
        : "=r"((r)[0]), "=r"((r)[1]), "=r"((r)[2]), "=r"((r)[3]) : "r"(addr))

#define MMA(c, a, b) \
    asm volatile("mma.sync.aligned.m16n8k16.row.col.f32.bf16.bf16.f32 " \
        "{%0,%1,%2,%3}, {%4,%5,%6,%7}, {%8,%9}, {%0,%1,%2,%3};" \
        : "+f"((c)[0]), "+f"((c)[1]), "+f"((c)[2]), "+f"((c)[3]) \
        : "r"((a)[0]), "r"((a)[1]), "r"((a)[2]), "r"((a)[3]), "r"((b)[0]), "r"((b)[1]))

#define CP_ASYNC16(dst, src) \
    asm volatile("cp.async.cg.shared.global [%0], [%1], 16;" :: "r"(dst), "l"(src) : "memory")
#define CP_COMMIT() asm volatile("cp.async.commit_group;" ::: "memory")
#define CP_WAIT0()  asm volatile("cp.async.wait_group 0;" ::: "memory")
#define CP_WAIT1()  asm volatile("cp.async.wait_group 1;" ::: "memory")

// ---------------- scratch (device globals) ----------------
__device__ __align__(256) __nv_bfloat16 g_xh[(size_t)NTOK * DMODEL];
__device__ __align__(256) __nv_bfloat16 g_xl[(size_t)NTOK * DMODEL];
__device__ __align__(256) __nv_bfloat16 g_wqkvh[(size_t)4 * 3072 * 1024];
__device__ __align__(256) __nv_bfloat16 g_wqkvl[(size_t)4 * 3072 * 1024];
__device__ __align__(256) __nv_bfloat16 g_woh[(size_t)4 * 1024 * 1024];
__device__ __align__(256) __nv_bfloat16 g_wol[(size_t)4 * 1024 * 1024];
__device__ __align__(256) __nv_bfloat16 g_wgh[(size_t)4096 * 4096];
__device__ __align__(256) __nv_bfloat16 g_wgl[(size_t)4096 * 4096];
__device__ __align__(256) __nv_bfloat16 g_wouth[(size_t)1024 * 4096];
__device__ __align__(256) __nv_bfloat16 g_woutl[(size_t)1024 * 4096];
__device__ __align__(256) __nv_bfloat16 g_qkvh[(size_t)NTOK * 3072];
__device__ __align__(256) __nv_bfloat16 g_qkvl[(size_t)NTOK * 3072];
__device__ __align__(256) __nv_bfloat16 g_attnh[(size_t)NTOK * 1024];
__device__ __align__(256) __nv_bfloat16 g_attnl[(size_t)NTOK * 1024];
__device__ __align__(256) __nv_bfloat16 g_conch[(size_t)NTOK * 4096];
__device__ __align__(256) __nv_bfloat16 g_concl[(size_t)NTOK * 4096];
__device__ __align__(256) __nv_bfloat16 g_gath[(size_t)NTOK * 4096];
__device__ __align__(256) __nv_bfloat16 g_gatl[(size_t)NTOK * 4096];
__device__ __align__(256) float g_fused[(size_t)NTOK * 1024];

// ---------------- fp32 -> bf16 hi/lo split ----------------
__global__ __launch_bounds__(256) void convert_split(
    const float* __restrict__ in, __nv_bfloat16* __restrict__ h,
    __nv_bfloat16* __restrict__ l, int n)
{
    for (int i = blockIdx.x * 256 + threadIdx.x; i < n; i += gridDim.x * 256) {
        float v = in[i];
        __nv_bfloat16 hh = __float2bfloat16(v);
        h[i] = hh;
        l[i] = __float2bfloat16(v - __bfloat162float(hh));
    }
}

// =================================================================================
// HMMA bf16 3-term GEMM, CTA tile 128x256, K-step 32, 3-stage cp.async.
// C[m][coff+n] = sum_k A[m][k]*B[n][k]
// mode 0: Cf = acc; mode 1: (Ch,Cl)=split(acc); mode 2: sigmoid-gate epilogue
// Stage layout (48KB): Ah[128x32] Al Bh[256x32] Bl, bf16, 64B rows, XOR swizzle.
// =================================================================================
#define STAGEB 49152
#define GSMEM  (3 * STAGEB)

__device__ __forceinline__ void load_stage(
    const __nv_bfloat16* __restrict__ Ah, const __nv_bfloat16* __restrict__ Al,
    const __nv_bfloat16* __restrict__ Bh, const __nv_bfloat16* __restrict__ Bl,
    int K, int k0, int bm, int bn, uint32_t sstage, int tid)
{
#pragma unroll
    for (int it = 0; it < 12; it++) {
        int idx = tid + it * 256;
        const __nv_bfloat16* src;
        uint32_t toff;
        int r, c;
        if (idx < 1024) {
            int half = idx >> 9;
            r = (idx >> 2) & 127; c = idx & 3;
            src = (half ? Al : Ah) + (size_t)(bm + r) * K + k0 + c * 8;
            toff = half * 8192;
        } else {
            int j = idx - 1024;
            int half = j >> 10;
            r = (j >> 2) & 255; c = j & 3;
            src = (half ? Bl : Bh) + (size_t)(bn + r) * K + k0 + c * 8;
            toff = 16384 + half * 16384;
        }
        uint32_t dst = sstage + toff + r * 64 + ((c ^ ((r >> 1) & 3)) << 4);
        CP_ASYNC16(dst, src);
    }
    CP_COMMIT();
}

__global__ __launch_bounds__(256, 1) void gemm_bf16(
    const __nv_bfloat16* __restrict__ Ah, const __nv_bfloat16* __restrict__ Al,
    const __nv_bfloat16* __restrict__ Bh, const __nv_bfloat16* __restrict__ Bl,
    int K, int mode,
    float* __restrict__ Cf,
    __nv_bfloat16* __restrict__ Ch, __nv_bfloat16* __restrict__ Cl,
    const float* __restrict__ bias,
    const __nv_bfloat16* __restrict__ Xh, const __nv_bfloat16* __restrict__ Xl,
    int ldc, int coff)
{
    extern __shared__ char smem[];
    const uint32_t sb = smem_u32(smem);
    const int tid = threadIdx.x;
    const int wid = tid >> 5, lane = tid & 31;
    const int bm = blockIdx.y * 128;
    const int bn = blockIdx.x * 256;
    const int wm = (wid & 1) * 64;
    const int wn = (wid >> 1) * 64;

    float acc[4][8][4];
#pragma unroll
    for (int mi = 0; mi < 4; mi++)
#pragma unroll
        for (int nj = 0; nj < 8; nj++)
#pragma unroll
            for (int q = 0; q < 4; q++) acc[mi][nj][q] = 0.f;

    const int nchunk = K >> 5;
    load_stage(Ah, Al, Bh, Bl, K, 0, bm, bn, sb, tid);
    load_stage(Ah, Al, Bh, Bl, K, 32, bm, bn, sb + STAGEB, tid);

    for (int i = 0; i < nchunk; i++) {
        if (i + 1 < nchunk) CP_WAIT1(); else CP_WAIT0();
        __syncthreads();
        if (i + 2 < nchunk)
            load_stage(Ah, Al, Bh, Bl, K, (i + 2) << 5, bm, bn,
                       sb + ((i + 2) % 3) * STAGEB, tid);

        const uint32_t st = sb + (i % 3) * STAGEB;
#pragma unroll
        for (int ks = 0; ks < 2; ks++) {
            uint32_t ah[4][4], al[4][4], bh[4][4], bl[4][4];
#pragma unroll
            for (int mi = 0; mi < 4; mi++) {
                int row = wm + mi * 16 + (lane & 15);
                int ch = (lane >> 4) + ks * 2;
                uint32_t ad = st + row * 64 + ((ch ^ ((row >> 1) & 3)) << 4);
                LDSM4(ah[mi], ad);
                LDSM4(al[mi], ad + 8192);
            }
#pragma unroll
            for (int nb = 0; nb < 4; nb++) {
                int row = wn + nb * 16 + (lane & 7) + ((lane >> 4) << 3);
                int ch = ((lane >> 3) & 1) + ks * 2;
                uint32_t ad = st + 16384 + row * 64 + ((ch ^ ((row >> 1) & 3)) << 4);
                LDSM4(bh[nb], ad);
                LDSM4(bl[nb], ad + 16384);
            }
#pragma unroll
            for (int mi = 0; mi < 4; mi++)
#pragma unroll
                for (int nj = 0; nj < 8; nj++) {
                    uint32_t* bhp = &bh[nj >> 1][(nj & 1) * 2];
                    uint32_t* blp = &bl[nj >> 1][(nj & 1) * 2];
                    MMA(acc[mi][nj], ah[mi], bhp);
                    MMA(acc[mi][nj], ah[mi], blp);
                    MMA(acc[mi][nj], al[mi], bhp);
                }
        }
    }

    // epilogue
#pragma unroll
    for (int mi = 0; mi < 4; mi++) {
#pragma unroll
        for (int r = 0; r < 2; r++) {
            int m = bm + wm + mi * 16 + (lane >> 2) + r * 8;
#pragma unroll
            for (int nj = 0; nj < 8; nj++) {
                int n = bn + wn + nj * 8 + (lane & 3) * 2;
                float v0 = acc[mi][nj][r * 2 + 0];
                float v1 = acc[mi][nj][r * 2 + 1];
                size_t o = (size_t)m * ldc + coff + n;
                if (mode == 0) {
                    *(float2*)(Cf + o) = make_float2(v0, v1);
                } else {
                    if (mode == 2) {
                        float g0 = 1.f / (1.f + __expf(-(v0 + bias[n])));
                        float g1 = 1.f / (1.f + __expf(-(v1 + bias[n + 1])));
                        float a0 = __bfloat162float(Xh[o]) + __bfloat162float(Xl[o]);
                        float a1 = __bfloat162float(Xh[o + 1]) + __bfloat162float(Xl[o + 1]);
                        v0 = g0 * a0; v1 = g1 * a1;
                    }
                    __nv_bfloat16 h0 = __float2bfloat16(v0);
                    __nv_bfloat16 h1 = __float2bfloat16(v1);
                    __nv_bfloat16 l0 = __float2bfloat16(v0 - __bfloat162float(h0));
                    __nv_bfloat16 l1 = __float2bfloat16(v1 - __bfloat162float(h1));
                    __nv_bfloat162 hp; hp.x = h0; hp.y = h1;
                    __nv_bfloat162 lp; lp.x = l0; lp.y = l1;
                    *(__nv_bfloat162*)(Ch + o) = hp;
                    *(__nv_bfloat162*)(Cl + o) = lp;
                }
            }
        }
    }
}

// =================================================================================
// Flash attention, HMMA bf16 3-term split.
// qkvh/qkvl: [NTOK][3072] bf16 hi/lo (q at h*64, k at 1024+h*64, v at 2048+h*64)
// attnh/attnl out: [NTOK][1024] bf16 hi/lo
// Block: 128 threads (4 warps), one (b,h,qtile64). Warp = 16 q-rows.
// Smem: Qh Ql Kh Kl Vh Vl Ph Pl, each 64 rows x 128B, XOR-8 swizzle. 64KB.
// =================================================================================
#define ATTN_SMEM 65536

__global__ __launch_bounds__(128) void attn_kernel(
    const __nv_bfloat16* __restrict__ qkvh, const __nv_bfloat16* __restrict__ qkvl,
    __nv_bfloat16* __restrict__ attnh, __nv_bfloat16* __restrict__ attnl,
    int tr, int rev)
{
    extern __shared__ char smem[];
    const uint32_t sb = smem_u32(smem);
    const int qt = blockIdx.x;
    const int b  = blockIdx.y >> 4;
    const int h  = blockIdx.y & 15;
    const int tid = threadIdx.x;
    const int wid = tid >> 5, lane = tid & 31;
    const size_t bq = (size_t)b * TSEQ;
    // smem offsets
    const uint32_t sQh = sb, sQl = sb + 8192, sKh = sb + 16384, sKl = sb + 24576;
    const uint32_t sVh = sb + 32768, sVl = sb + 40960, sPh = sb + 49152, sPl = sb + 57344;

    // ---- load Q (scaled by 1/8, permuted gather) ----
    {
        const __nv_bfloat162 s2 = __float2bfloat162_rn(0.125f);
        for (int i = tid; i < 1024; i += 128) {
            int half = i >> 9;
            int j = i & 511;
            int row = j >> 3, c = j & 7;
            int t = qt * 64 + row;
            int tok = tr ? ((t & 31) * 32 + (t >> 5)) : t;
            const __nv_bfloat16* src = (half ? qkvl : qkvh) + (bq + tok) * 3072 + h * 64 + c * 8;
            uint4 v = *(const uint4*)src;
            __nv_bfloat162* p2 = (__nv_bfloat162*)&v;
#pragma unroll
            for (int q = 0; q < 4; q++) p2[q] = __hmul2(p2[q], s2);
            uint32_t off = half * 8192 + row * 128 + ((c ^ (row & 7)) << 4);
            *(uint4*)(smem + off) = v;
        }
    }

    float m0[2] = {-1e30f, -1e30f}, l0[2] = {0.f, 0.f};
    float o[8][4];
#pragma unroll
    for (int nj = 0; nj < 8; nj++)
#pragma unroll
        for (int q = 0; q < 4; q++) o[nj][q] = 0.f;

    const int kt_lo = rev ? qt : 0;
    const int kt_hi = rev ? 15 : qt;

    for (int kt = kt_lo; kt <= kt_hi; kt++) {
        __syncthreads();   // all warps done with previous K/V
        // ---- load K,V hi/lo via cp.async ----
        for (int i = tid; i < 2048; i += 128) {
            int arr = i >> 9;              // 0:Kh 1:Kl 2:Vh 3:Vl
            int j = i & 511;
            int row = j >> 3, c = j & 7;
            int t = kt * 64 + row;
            int tok = tr ? ((t & 31) * 32 + (t >> 5)) : t;
            const __nv_bfloat16* src = ((arr & 1) ? qkvl : qkvh)
                + (bq + tok) * 3072 + 1024 + (arr >> 1) * 1024 + h * 64 + c * 8;
            uint32_t dst = sKh + arr * 8192 + row * 128 + ((c ^ (row & 7)) << 4);
            CP_ASYNC16(dst, src);
        }
        CP_COMMIT(); CP_WAIT0();
        __syncthreads();

        // ---- S = Q K^T (3-term) ----
        float s[8][4];
#pragma unroll
        for (int nj = 0; nj < 8; nj++)
#pragma unroll
            for (int q = 0; q < 4; q++) s[nj][q] = 0.f;
#pragma unroll
        for (int kk = 0; kk < 4; kk++) {
            uint32_t qh_f[4], ql_f[4];
            {
                int row = wid * 16 + (lane & 15);
                int ch = (lane >> 4) + kk * 2;
                uint32_t ad = row * 128 + ((ch ^ (row & 7)) << 4);
                LDSM4(qh_f, sQh + ad);
                LDSM4(ql_f, sQl + ad);
            }
#pragma unroll
            for (int nb = 0; nb < 4; nb++) {
                uint32_t kh_f[4], kl_f[4];
                int row = nb * 16 + (lane & 7) + ((lane >> 4) << 3);
                int ch = ((lane >> 3) & 1) + kk * 2;
                uint32_t ad = row * 128 + ((ch ^ (row & 7)) << 4);
                LDSM4(kh_f, sKh + ad);
                LDSM4(kl_f, sKl + ad);
#pragma unroll
                for (int half = 0; half < 2; half++) {
                    int nj = nb * 2 + half;
                    uint32_t* bhp = &kh_f[half * 2];
                    uint32_t* blp = &kl_f[half * 2];
                    MMA(s[nj], qh_f, bhp);
                    MMA(s[nj], qh_f, blp);
                    MMA(s[nj], ql_f, bhp);
                }
            }
        }

        // ---- mask (diagonal tile) ----
        if (kt == qt) {
#pragma unroll
            for (int nj = 0; nj < 8; nj++)
#pragma unroll
                for (int q = 0; q < 4; q++) {
                    int rr = q >> 1;
                    int qi = qt * 64 + wid * 16 + (lane >> 2) + rr * 8;
                    int ki = kt * 64 + nj * 8 + (lane & 3) * 2 + (q & 1);
                    bool valid = rev ? (ki >= qi) : (ki <= qi);
                    if (!valid) s[nj][q] = -1e30f;
                }
        }

        // ---- online softmax + P write ----
#pragma unroll
        for (int rr = 0; rr < 2; rr++) {
            float vm = -1e30f;
#pragma unroll
            for (int nj = 0; nj < 8; nj++) {
                vm = fmaxf(vm, s[nj][rr * 2 + 0]);
                vm = fmaxf(vm, s[nj][rr * 2 + 1]);
            }
            vm = fmaxf(vm, __shfl_xor_sync(0xffffffffu, vm, 1));
            vm = fmaxf(vm, __shfl_xor_sync(0xffffffffu, vm, 2));
            float mn = fmaxf(m0[rr], vm);
            float fac = __expf(m0[rr] - mn);
            float rs = 0.f;
            int qrow = wid * 16 + (lane >> 2) + rr * 8;
#pragma unroll
            for (int nj = 0; nj < 8; nj++) {
                float p0 = __expf(s[nj][rr * 2 + 0] - mn);
                float p1 = __expf(s[nj][rr * 2 + 1] - mn);
                rs += p0 + p1;
                __nv_bfloat16 h0 = __float2bfloat16(p0);
                __nv_bfloat16 h1 = __float2bfloat16(p1);
                __nv_bfloat16 e0 = __float2bfloat16(p0 - __bfloat162float(h0));
                __nv_bfloat16 e1 = __float2bfloat16(p1 - __bfloat162float(h1));
                uint32_t off = qrow * 128 + ((nj ^ (qrow & 7)) << 4) + (lane & 3) * 4;
                __nv_bfloat162 hp; hp.x = h0; hp.y = h1;
                __nv_bfloat162 lp; lp.x = e0; lp.y = e1;
                *(__nv_bfloat162*)(smem + (sPh - sb) + off) = hp;
                *(__nv_bfloat162*)(smem + (sPl - sb) + off) = lp;
            }
            rs += __shfl_xor_sync(0xffffffffu, rs, 1);
            rs += __shfl_xor_sync(0xffffffffu, rs, 2);
            l0[rr] = l0[rr] * fac + rs;
            m0[rr] = mn;
#pragma unroll
            for (int nj = 0; nj < 8; nj++) {
                o[nj][rr * 2 + 0] *= fac;
                o[nj][rr * 2 + 1] *= fac;
            }
        }

        // ---- O += P V (3-term; A = P rows of this warp, B = V^T via ldsm.trans) ----
#pragma unroll
        for (int kk = 0; kk < 4; kk++) {
            uint32_t ph_f[4], pl_f[4];
            {
                int row = wid * 16 + (lane & 15);
                int ch = (lane >> 4) + kk * 2;
                uint32_t ad = row * 128 + ((ch ^ (row & 7)) << 4);
                LDSM4(ph_f, sPh + ad);
                LDSM4(pl_f, sPl + ad);
            }
#pragma unroll
            for (int nb = 0; nb < 4; nb++) {
                uint32_t vh_f[4], vl_f[4];
                int row = kk * 16 + (lane & 15);
                int ch = (nb * 2 + (lane >> 4)) ^ (row & 7);
                uint32_t ad = row * 128 + (ch << 4);
                LDSM4T(vh_f, sVh + ad);
                LDSM4T(vl_f, sVl + ad);
#pragma unroll
                for (int half = 0; half < 2; half++) {
                    int nj = nb * 2 + half;
                    uint32_t* bhp = &vh_f[half * 2];
                    uint32_t* blp = &vl_f[half * 2];
                    MMA(o[nj], ph_f, bhp);
                    MMA(o[nj], ph_f, blp);
                    MMA(o[nj], pl_f, bhp);
                }
            }
        }
    }

    // ---- normalize + split + permuted scatter ----
#pragma unroll
    for (int rr = 0; rr < 2; rr++) {
        float inv = 1.f / l0[rr];
        int qrow = wid * 16 + (lane >> 2) + rr * 8;
        int t = qt * 64 + qrow;
        int tok = tr ? ((t & 31) * 32 + (t >> 5)) : t;
        size_t base = (bq + tok) * 1024 + h * 64;
#pragma unroll
        for (int nj = 0; nj < 8; nj++) {
            int d = nj * 8 + (lane & 3) * 2;
            float v0 = o[nj][rr * 2 + 0] * inv;
            float v1 = o[nj][rr * 2 + 1] * inv;
            __nv_bfloat16 h0 = __float2bfloat16(v0);
            __nv_bfloat16 h1 = __float2bfloat16(v1);
            __nv_bfloat16 e0 = __float2bfloat16(v0 - __bfloat162float(h0));
            __nv_bfloat16 e1 = __float2bfloat16(v1 - __bfloat162float(h1));
            __nv_bfloat162 hp; hp.x = h0; hp.y = h1;
            __nv_bfloat162 lp; lp.x = e0; lp.y = e1;
            *(__nv_bfloat162*)(attnh + base + d) = hp;
            *(__nv_bfloat162*)(attnl + base + d) = lp;
        }
    }
}

// =================================================================================
// RMSNorm epilogue
// =================================================================================
__global__ __launch_bounds__(256) void rmsnorm_kernel(
    const float* __restrict__ fused, const float* __restrict__ x,
    const float* __restrict__ w, float* __restrict__ out)
{
    const int t = blockIdx.x;
    const int tid = threadIdx.x;
    const float* fr = fused + (size_t)t * 1024;
    const float* xr = x + (size_t)t * 1024;
    float y[4];
    float ss = 0.f;
#pragma unroll
    for (int i = 0; i < 4; i++) {
        int c = tid + i * 256;
        y[i] = fr[c] + xr[c];
        ss += y[i] * y[i];
    }
#pragma unroll
    for (int off = 16; off >= 1; off >>= 1)
        ss += __shfl_xor_sync(0xffffffffu, ss, off);
    __shared__ float red[8];
    if ((tid & 31) == 0) red[tid >> 5] = ss;
    __syncthreads();
    float tot = red[0] + red[1] + red[2] + red[3] + red[4] + red[5] + red[6] + red[7];
    float r = rsqrtf(tot * (1.f / 1024.f) + 1e-6f);
    float* orow = out + (size_t)t * 1024;
#pragma unroll
    for (int i = 0; i < 4; i++) {
        int c = tid + i * 256;
        orow[c] = y[i] * r * w[c];
    }
}

// =================================================================================
// Launch
// =================================================================================
extern "C" void kernel_launch(void* const* d_in, const int* in_sizes, int n_in,
                              void* d_out, int out_size)
{
    const float* x       = (const float*)d_in[0];
    const float* w_qkv[4] = { (const float*)d_in[1], (const float*)d_in[3],
                              (const float*)d_in[5], (const float*)d_in[7] };
    const float* w_o[4]   = { (const float*)d_in[2], (const float*)d_in[4],
                              (const float*)d_in[6], (const float*)d_in[8] };
    const float* w_gate  = (const float*)d_in[9];
    const float* b_gate  = (const float*)d_in[10];
    const float* w_out   = (const float*)d_in[11];
    const float* norm_w  = (const float*)d_in[12];
    float* out = (float*)d_out;

    __nv_bfloat16 *xh, *xl, *wqkvh, *wqkvl, *woh, *wol, *wgh, *wgl, *wouth, *woutl;
    __nv_bfloat16 *qkvh, *qkvl, *attnh, *attnl, *conch, *concl, *gath, *gatl;
    float *fused;
    cudaGetSymbolAddress((void**)&xh, g_xh);       cudaGetSymbolAddress((void**)&xl, g_xl);
    cudaGetSymbolAddress((void**)&wqkvh, g_wqkvh); cudaGetSymbolAddress((void**)&wqkvl, g_wqkvl);
    cudaGetSymbolAddress((void**)&woh, g_woh);     cudaGetSymbolAddress((void**)&wol, g_wol);
    cudaGetSymbolAddress((void**)&wgh, g_wgh);     cudaGetSymbolAddress((void**)&wgl, g_wgl);
    cudaGetSymbolAddress((void**)&wouth, g_wouth); cudaGetSymbolAddress((void**)&woutl, g_woutl);
    cudaGetSymbolAddress((void**)&qkvh, g_qkvh);   cudaGetSymbolAddress((void**)&qkvl, g_qkvl);
    cudaGetSymbolAddress((void**)&attnh, g_attnh); cudaGetSymbolAddress((void**)&attnl, g_attnl);
    cudaGetSymbolAddress((void**)&conch, g_conch); cudaGetSymbolAddress((void**)&concl, g_concl);
    cudaGetSymbolAddress((void**)&gath, g_gath);   cudaGetSymbolAddress((void**)&gatl, g_gatl);
    cudaGetSymbolAddress((void**)&fused, g_fused);

    cudaFuncSetAttribute(attn_kernel, cudaFuncAttributeMaxDynamicSharedMemorySize, ATTN_SMEM);
    cudaFuncSetAttribute(gemm_bf16, cudaFuncAttributeMaxDynamicSharedMemorySize, GSMEM);

    convert_split<<<2048, 256>>>(x, xh, xl, NTOK * DMODEL);
    for (int d = 0; d < 4; d++) {
        convert_split<<<2048, 256>>>(w_qkv[d], wqkvh + (size_t)d * 3072 * 1024,
                                     wqkvl + (size_t)d * 3072 * 1024, 3072 * 1024);
        convert_split<<<2048, 256>>>(w_o[d], woh + (size_t)d * 1024 * 1024,
                                     wol + (size_t)d * 1024 * 1024, 1024 * 1024);
    }
    convert_split<<<4096, 256>>>(w_gate, wgh, wgl, 4096 * 4096);
    convert_split<<<2048, 256>>>(w_out, wouth, woutl, 1024 * 4096);

    for (int dir = 0; dir < 4; dir++) {
        const int tr  = (dir >= 2) ? 1 : 0;
        const int rev = (dir & 1);

        // QKV: x @ w_qkv^T -> qkv (bf16 hi/lo)
        gemm_bf16<<<dim3(3072 / 256, 4096 / 128), 256, GSMEM>>>(
            xh, xl, wqkvh + (size_t)dir * 3072 * 1024, wqkvl + (size_t)dir * 3072 * 1024,
            1024, 1, nullptr, qkvh, qkvl, nullptr, nullptr, nullptr, 3072, 0);

        attn_kernel<<<dim3(16, 4 * NH), 128, ATTN_SMEM>>>(qkvh, qkvl, attnh, attnl, tr, rev);

        // O-proj -> concat block (bf16 hi/lo)
        gemm_bf16<<<dim3(1024 / 256, 4096 / 128), 256, GSMEM>>>(
            attnh, attnl, woh + (size_t)dir * 1024 * 1024, wol + (size_t)dir * 1024 * 1024,
            1024, 1, nullptr, conch, concl, nullptr, nullptr, nullptr, 4096, dir * 1024);
    }

    // gate: sigmoid(concat @ w_gate^T + b) * concat -> gated
    gemm_bf16<<<dim3(4096 / 256, 4096 / 128), 256, GSMEM>>>(
        conch, concl, wgh, wgl, 4096, 2, nullptr, gath, gatl, b_gate, conch, concl, 4096, 0);

    // out: gated @ w_out^T -> fused fp32
    gemm_bf16<<<dim3(1024 / 256, 4096 / 128), 256, GSMEM>>>(
        gath, gatl, wouth, woutl, 4096, 0, fused, nullptr, nullptr, nullptr, nullptr, nullptr, 1024, 0);

    rmsnorm_kernel<<<NTOK, 256>>>(fused, x, norm_w, out);
}

// round 5
// speedup vs baseline: 1.6296x; 1.6296x over previous
#include <cuda_runtime.h>
#include <cuda_bf16.h>
#include <math.h>
#include <stdint.h>

#define NTOK 4096
#define DMODEL 1024
#define NH 16
#define TSEQ 1024

// ---------------- helpers ----------------
__device__ __forceinline__ uint32_t smem_u32(const void* p) {
    uint32_t a;
    asm("{ .reg .u64 t; cvta.to.shared.u64 t, %1; cvt.u32.u64 %0, t; }" : "=r"(a) : "l"(p));
    return a;
}

#define LDSM4(r, addr) \
    asm volatile("ldmatrix.sync.aligned.m8n8.x4.shared.b16 {%0,%1,%2,%3}, [%4];" \
        : "=r"((r)[0]), "=r"((r)[1]), "=r"((r)[2]), "=r"((r)[3]) : "r"(addr))

#define LDSM4T(r, addr) \
    asm volatile("ldmatrix.sync.aligned.m8n8.x4.trans.shared.b16 {%0,%1,%2,%3}, [%4];" \
        : "=r"((r)[0]), "=r"((r)[1]), "=r"((r)[2]), "=r"((r)[3]) : "r"(addr))

#define MMA(c, a, b) \
    asm volatile("mma.sync.aligned.m16n8k16.row.col.f32.bf16.bf16.f32 " \
        "{%0,%1,%2,%3}, {%4,%5,%6,%7}, {%8,%9}, {%0,%1,%2,%3};" \
        : "+f"((c)[0]), "+f"((c)[1]), "+f"((c)[2]), "+f"((c)[3]) \
        : "r"((a)[0]), "r"((a)[1]), "r"((a)[2]), "r"((a)[3]), "r"((b)[0]), "r"((b)[1]))

#define CP_ASYNC16(dst, src) \
    asm volatile("cp.async.cg.shared.global [%0], [%1], 16;" :: "r"(dst), "l"(src) : "memory")
#define CP_COMMIT() asm volatile("cp.async.commit_group;" ::: "memory")
#define CP_WAIT0()  asm volatile("cp.async.wait_group 0;" ::: "memory")
#define CP_WAIT1()  asm volatile("cp.async.wait_group 1;" ::: "memory")

// ---------------- scratch (device globals) ----------------
__device__ __align__(256) __nv_bfloat16 g_xh[(size_t)NTOK * DMODEL];
__device__ __align__(256) __nv_bfloat16 g_xl[(size_t)NTOK * DMODEL];
__device__ __align__(256) __nv_bfloat16 g_wqkvh[(size_t)4 * 3072 * 1024];
__device__ __align__(256) __nv_bfloat16 g_wqkvl[(size_t)4 * 3072 * 1024];
__device__ __align__(256) __nv_bfloat16 g_woh[(size_t)4 * 1024 * 1024];
__device__ __align__(256) __nv_bfloat16 g_wol[(size_t)4 * 1024 * 1024];
__device__ __align__(256) __nv_bfloat16 g_wgh[(size_t)4096 * 4096];
__device__ __align__(256) __nv_bfloat16 g_wgl[(size_t)4096 * 4096];
__device__ __align__(256) __nv_bfloat16 g_wouth[(size_t)1024 * 4096];
__device__ __align__(256) __nv_bfloat16 g_woutl[(size_t)1024 * 4096];
__device__ __align__(256) __nv_bfloat16 g_qkvh[(size_t)NTOK * 3072];
__device__ __align__(256) __nv_bfloat16 g_qkvl[(size_t)NTOK * 3072];
__device__ __align__(256) __nv_bfloat16 g_attnh[(size_t)NTOK * 1024];
__device__ __align__(256) __nv_bfloat16 g_attnl[(size_t)NTOK * 1024];
__device__ __align__(256) __nv_bfloat16 g_conch[(size_t)NTOK * 4096];
__device__ __align__(256) __nv_bfloat16 g_concl[(size_t)NTOK * 4096];
__device__ __align__(256) __nv_bfloat16 g_gath[(size_t)NTOK * 4096];
__device__ __align__(256) __nv_bfloat16 g_gatl[(size_t)NTOK * 4096];
__device__ __align__(256) float g_fused[(size_t)NTOK * 1024];

// ---------------- fp32 -> bf16 hi/lo split ----------------
__global__ __launch_bounds__(256) void convert_split(
    const float* __restrict__ in, __nv_bfloat16* __restrict__ h,
    __nv_bfloat16* __restrict__ l, int n)
{
    for (int i = blockIdx.x * 256 + threadIdx.x; i < n; i += gridDim.x * 256) {
        float v = in[i];
        __nv_bfloat16 hh = __float2bfloat16(v);
        h[i] = hh;
        l[i] = __float2bfloat16(v - __bfloat162float(hh));
    }
}

// =================================================================================
// HMMA bf16 3-term split GEMM (R3-proven config): CTA 128x128, K-step 32,
// 2-stage cp.async double buffer, ldmatrix + mma.sync m16n8k16.
// mode 0: Cf = acc (fp32)
// mode 1: (Ch,Cl) = split(acc)
// mode 2: g = sigmoid(acc + bias[n]); (Ch,Cl) = split(g * (Xh+Xl)[m][n])
// =================================================================================
#define STAGEB 32768
#define GSMEM  (2 * STAGEB)

__device__ __forceinline__ void load_stage(
    const __nv_bfloat16* __restrict__ Ah, const __nv_bfloat16* __restrict__ Al,
    const __nv_bfloat16* __restrict__ Bh, const __nv_bfloat16* __restrict__ Bl,
    int K, int k0, int bm, int bn, uint32_t sstage, int tid)
{
#pragma unroll
    for (int it = 0; it < 8; it++) {
        int cidx = tid + it * 256;
        int t = cidx >> 9;
        int row = (cidx >> 2) & 127;
        int c = cidx & 3;
        const __nv_bfloat16* src = (t == 0) ? Ah : (t == 1) ? Al : (t == 2) ? Bh : Bl;
        int rb = (t < 2) ? bm : bn;
        const __nv_bfloat16* gsrc = src + (size_t)(rb + row) * K + k0 + c * 8;
        uint32_t dst = sstage + t * 8192 + row * 64 + ((c ^ ((row >> 1) & 3)) << 4);
        CP_ASYNC16(dst, gsrc);
    }
    CP_COMMIT();
}

__global__ __launch_bounds__(256) void gemm_bf16(
    const __nv_bfloat16* __restrict__ Ah, const __nv_bfloat16* __restrict__ Al,
    const __nv_bfloat16* __restrict__ Bh, const __nv_bfloat16* __restrict__ Bl,
    int K, int mode,
    float* __restrict__ Cf,
    __nv_bfloat16* __restrict__ Ch, __nv_bfloat16* __restrict__ Cl,
    const float* __restrict__ bias,
    const __nv_bfloat16* __restrict__ Xh, const __nv_bfloat16* __restrict__ Xl,
    int ldc, int coff)
{
    extern __shared__ char smem[];
    const uint32_t sb = smem_u32(smem);
    const int tid = threadIdx.x;
    const int wid = tid >> 5, lane = tid & 31;
    const int bm = blockIdx.y * 128;
    const int bn = blockIdx.x * 128;
    const int wm = (wid >> 2) * 64;
    const int wn = (wid & 3) * 32;

    float acc[4][4][4];
#pragma unroll
    for (int mi = 0; mi < 4; mi++)
#pragma unroll
        for (int nj = 0; nj < 4; nj++)
#pragma unroll
            for (int q = 0; q < 4; q++) acc[mi][nj][q] = 0.f;

    const int nchunk = K >> 5;
    load_stage(Ah, Al, Bh, Bl, K, 0, bm, bn, sb, tid);

    for (int i = 0; i < nchunk; i++) {
        if (i + 1 < nchunk) {
            load_stage(Ah, Al, Bh, Bl, K, (i + 1) << 5, bm, bn,
                       sb + ((i + 1) & 1) * STAGEB, tid);
            CP_WAIT1();
        } else {
            CP_WAIT0();
        }
        __syncthreads();

        const uint32_t st = sb + (i & 1) * STAGEB;
#pragma unroll
        for (int ks = 0; ks < 2; ks++) {
            uint32_t ah[4][4], al[4][4], bh[2][4], bl[2][4];
#pragma unroll
            for (int mi = 0; mi < 4; mi++) {
                int row = wm + mi * 16 + (lane & 7) + (((lane >> 3) & 1) << 3);
                int ch = (lane >> 4) + ks * 2;
                uint32_t ad = st + row * 64 + ((ch ^ ((row >> 1) & 3)) << 4);
                LDSM4(ah[mi], ad);
                LDSM4(al[mi], ad + 8192);
            }
#pragma unroll
            for (int nb = 0; nb < 2; nb++) {
                int row = wn + nb * 16 + (lane & 7) + ((lane >> 4) << 3);
                int ch = ((lane >> 3) & 1) + ks * 2;
                uint32_t ad = st + 16384 + row * 64 + ((ch ^ ((row >> 1) & 3)) << 4);
                LDSM4(bh[nb], ad);
                LDSM4(bl[nb], ad + 8192);
            }
#pragma unroll
            for (int mi = 0; mi < 4; mi++)
#pragma unroll
                for (int nj = 0; nj < 4; nj++) {
                    uint32_t* bhp = &bh[nj >> 1][(nj & 1) * 2];
                    uint32_t* blp = &bl[nj >> 1][(nj & 1) * 2];
                    MMA(acc[mi][nj], ah[mi], bhp);
                    MMA(acc[mi][nj], ah[mi], blp);
                    MMA(acc[mi][nj], al[mi], bhp);
                }
        }
        __syncthreads();
    }

    // epilogue
#pragma unroll
    for (int mi = 0; mi < 4; mi++) {
#pragma unroll
        for (int r = 0; r < 2; r++) {
            int m = bm + wm + mi * 16 + (lane >> 2) + r * 8;
#pragma unroll
            for (int nj = 0; nj < 4; nj++) {
                int n = bn + wn + nj * 8 + (lane & 3) * 2;
                float v0 = acc[mi][nj][r * 2 + 0];
                float v1 = acc[mi][nj][r * 2 + 1];
                size_t o = (size_t)m * ldc + coff + n;
                if (mode == 0) {
                    *(float2*)(Cf + o) = make_float2(v0, v1);
                } else {
                    if (mode == 2) {
                        float g0 = 1.f / (1.f + __expf(-(v0 + bias[n])));
                        float g1 = 1.f / (1.f + __expf(-(v1 + bias[n + 1])));
                        float a0 = __bfloat162float(Xh[o]) + __bfloat162float(Xl[o]);
                        float a1 = __bfloat162float(Xh[o + 1]) + __bfloat162float(Xl[o + 1]);
                        v0 = g0 * a0; v1 = g1 * a1;
                    }
                    __nv_bfloat16 h0 = __float2bfloat16(v0);
                    __nv_bfloat16 h1 = __float2bfloat16(v1);
                    __nv_bfloat16 l0 = __float2bfloat16(v0 - __bfloat162float(h0));
                    __nv_bfloat16 l1 = __float2bfloat16(v1 - __bfloat162float(h1));
                    __nv_bfloat162 hp; hp.x = h0; hp.y = h1;
                    __nv_bfloat162 lp; lp.x = l0; lp.y = l1;
                    *(__nv_bfloat162*)(Ch + o) = hp;
                    *(__nv_bfloat162*)(Cl + o) = lp;
                }
            }
        }
    }
}

// =================================================================================
// Flash attention, HMMA bf16 3-term split (unchanged from R4 — passed at 5.7e-7).
// =================================================================================
#define ATTN_SMEM 65536

__global__ __launch_bounds__(128) void attn_kernel(
    const __nv_bfloat16* __restrict__ qkvh, const __nv_bfloat16* __restrict__ qkvl,
    __nv_bfloat16* __restrict__ attnh, __nv_bfloat16* __restrict__ attnl,
    int tr, int rev)
{
    extern __shared__ char smem[];
    const uint32_t sb = smem_u32(smem);
    const int qt = blockIdx.x;
    const int b  = blockIdx.y >> 4;
    const int h  = blockIdx.y & 15;
    const int tid = threadIdx.x;
    const int wid = tid >> 5, lane = tid & 31;
    const size_t bq = (size_t)b * TSEQ;
    const uint32_t sQh = sb, sQl = sb + 8192, sKh = sb + 16384, sKl = sb + 24576;
    const uint32_t sVh = sb + 32768, sVl = sb + 40960, sPh = sb + 49152, sPl = sb + 57344;

    {
        const __nv_bfloat162 s2 = __float2bfloat162_rn(0.125f);
        for (int i = tid; i < 1024; i += 128) {
            int half = i >> 9;
            int j = i & 511;
            int row = j >> 3, c = j & 7;
            int t = qt * 64 + row;
            int tok = tr ? ((t & 31) * 32 + (t >> 5)) : t;
            const __nv_bfloat16* src = (half ? qkvl : qkvh) + (bq + tok) * 3072 + h * 64 + c * 8;
            uint4 v = *(const uint4*)src;
            __nv_bfloat162* p2 = (__nv_bfloat162*)&v;
#pragma unroll
            for (int q = 0; q < 4; q++) p2[q] = __hmul2(p2[q], s2);
            uint32_t off = half * 8192 + row * 128 + ((c ^ (row & 7)) << 4);
            *(uint4*)(smem + off) = v;
        }
    }

    float m0[2] = {-1e30f, -1e30f}, l0[2] = {0.f, 0.f};
    float o[8][4];
#pragma unroll
    for (int nj = 0; nj < 8; nj++)
#pragma unroll
        for (int q = 0; q < 4; q++) o[nj][q] = 0.f;

    const int kt_lo = rev ? qt : 0;
    const int kt_hi = rev ? 15 : qt;

    for (int kt = kt_lo; kt <= kt_hi; kt++) {
        __syncthreads();
        for (int i = tid; i < 2048; i += 128) {
            int arr = i >> 9;
            int j = i & 511;
            int row = j >> 3, c = j & 7;
            int t = kt * 64 + row;
            int tok = tr ? ((t & 31) * 32 + (t >> 5)) : t;
            const __nv_bfloat16* src = ((arr & 1) ? qkvl : qkvh)
                + (bq + tok) * 3072 + 1024 + (arr >> 1) * 1024 + h * 64 + c * 8;
            uint32_t dst = sKh + arr * 8192 + row * 128 + ((c ^ (row & 7)) << 4);
            CP_ASYNC16(dst, src);
        }
        CP_COMMIT(); CP_WAIT0();
        __syncthreads();

        float s[8][4];
#pragma unroll
        for (int nj = 0; nj < 8; nj++)
#pragma unroll
            for (int q = 0; q < 4; q++) s[nj][q] = 0.f;
#pragma unroll
        for (int kk = 0; kk < 4; kk++) {
            uint32_t qh_f[4], ql_f[4];
            {
                int row = wid * 16 + (lane & 15);
                int ch = (lane >> 4) + kk * 2;
                uint32_t ad = row * 128 + ((ch ^ (row & 7)) << 4);
                LDSM4(qh_f, sQh + ad);
                LDSM4(ql_f, sQl + ad);
            }
#pragma unroll
            for (int nb = 0; nb < 4; nb++) {
                uint32_t kh_f[4], kl_f[4];
                int row = nb * 16 + (lane & 7) + ((lane >> 4) << 3);
                int ch = ((lane >> 3) & 1) + kk * 2;
                uint32_t ad = row * 128 + ((ch ^ (row & 7)) << 4);
                LDSM4(kh_f, sKh + ad);
                LDSM4(kl_f, sKl + ad);
#pragma unroll
                for (int half = 0; half < 2; half++) {
                    int nj = nb * 2 + half;
                    uint32_t* bhp = &kh_f[half * 2];
                    uint32_t* blp = &kl_f[half * 2];
                    MMA(s[nj], qh_f, bhp);
                    MMA(s[nj], qh_f, blp);
                    MMA(s[nj], ql_f, bhp);
                }
            }
        }

        if (kt == qt) {
#pragma unroll
            for (int nj = 0; nj < 8; nj++)
#pragma unroll
                for (int q = 0; q < 4; q++) {
                    int rr = q >> 1;
                    int qi = qt * 64 + wid * 16 + (lane >> 2) + rr * 8;
                    int ki = kt * 64 + nj * 8 + (lane & 3) * 2 + (q & 1);
                    bool valid = rev ? (ki >= qi) : (ki <= qi);
                    if (!valid) s[nj][q] = -1e30f;
                }
        }

#pragma unroll
        for (int rr = 0; rr < 2; rr++) {
            float vm = -1e30f;
#pragma unroll
            for (int nj = 0; nj < 8; nj++) {
                vm = fmaxf(vm, s[nj][rr * 2 + 0]);
                vm = fmaxf(vm, s[nj][rr * 2 + 1]);
            }
            vm = fmaxf(vm, __shfl_xor_sync(0xffffffffu, vm, 1));
            vm = fmaxf(vm, __shfl_xor_sync(0xffffffffu, vm, 2));
            float mn = fmaxf(m0[rr], vm);
            float fac = __expf(m0[rr] - mn);
            float rs = 0.f;
            int qrow = wid * 16 + (lane >> 2) + rr * 8;
#pragma unroll
            for (int nj = 0; nj < 8; nj++) {
                float p0 = __expf(s[nj][rr * 2 + 0] - mn);
                float p1 = __expf(s[nj][rr * 2 + 1] - mn);
                rs += p0 + p1;
                __nv_bfloat16 h0 = __float2bfloat16(p0);
                __nv_bfloat16 h1 = __float2bfloat16(p1);
                __nv_bfloat16 e0 = __float2bfloat16(p0 - __bfloat162float(h0));
                __nv_bfloat16 e1 = __float2bfloat16(p1 - __bfloat162float(h1));
                uint32_t off = qrow * 128 + ((nj ^ (qrow & 7)) << 4) + (lane & 3) * 4;
                __nv_bfloat162 hp; hp.x = h0; hp.y = h1;
                __nv_bfloat162 lp; lp.x = e0; lp.y = e1;
                *(__nv_bfloat162*)(smem + (sPh - sb) + off) = hp;
                *(__nv_bfloat162*)(smem + (sPl - sb) + off) = lp;
            }
            rs += __shfl_xor_sync(0xffffffffu, rs, 1);
            rs += __shfl_xor_sync(0xffffffffu, rs, 2);
            l0[rr] = l0[rr] * fac + rs;
            m0[rr] = mn;
#pragma unroll
            for (int nj = 0; nj < 8; nj++) {
                o[nj][rr * 2 + 0] *= fac;
                o[nj][rr * 2 + 1] *= fac;
            }
        }

#pragma unroll
        for (int kk = 0; kk < 4; kk++) {
            uint32_t ph_f[4], pl_f[4];
            {
                int row = wid * 16 + (lane & 15);
                int ch = (lane >> 4) + kk * 2;
                uint32_t ad = row * 128 + ((ch ^ (row & 7)) << 4);
                LDSM4(ph_f, sPh + ad);
                LDSM4(pl_f, sPl + ad);
            }
#pragma unroll
            for (int nb = 0; nb < 4; nb++) {
                uint32_t vh_f[4], vl_f[4];
                int row = kk * 16 + (lane & 15);
                int ch = (nb * 2 + (lane >> 4)) ^ (row & 7);
                uint32_t ad = row * 128 + (ch << 4);
                LDSM4T(vh_f, sVh + ad);
                LDSM4T(vl_f, sVl + ad);
#pragma unroll
                for (int half = 0; half < 2; half++) {
                    int nj = nb * 2 + half;
                    uint32_t* bhp = &vh_f[half * 2];
                    uint32_t* blp = &vl_f[half * 2];
                    MMA(o[nj], ph_f, bhp);
                    MMA(o[nj], ph_f, blp);
                    MMA(o[nj], pl_f, bhp);
                }
            }
        }
    }

#pragma unroll
    for (int rr = 0; rr < 2; rr++) {
        float inv = 1.f / l0[rr];
        int qrow = wid * 16 + (lane >> 2) + rr * 8;
        int t = qt * 64 + qrow;
        int tok = tr ? ((t & 31) * 32 + (t >> 5)) : t;
        size_t base = (bq + tok) * 1024 + h * 64;
#pragma unroll
        for (int nj = 0; nj < 8; nj++) {
            int d = nj * 8 + (lane & 3) * 2;
            float v0 = o[nj][rr * 2 + 0] * inv;
            float v1 = o[nj][rr * 2 + 1] * inv;
            __nv_bfloat16 h0 = __float2bfloat16(v0);
            __nv_bfloat16 h1 = __float2bfloat16(v1);
            __nv_bfloat16 e0 = __float2bfloat16(v0 - __bfloat162float(h0));
            __nv_bfloat16 e1 = __float2bfloat16(v1 - __bfloat162float(h1));
            __nv_bfloat162 hp; hp.x = h0; hp.y = h1;
            __nv_bfloat162 lp; lp.x = e0; lp.y = e1;
            *(__nv_bfloat162*)(attnh + base + d) = hp;
            *(__nv_bfloat162*)(attnl + base + d) = lp;
        }
    }
}

// =================================================================================
// RMSNorm epilogue
// =================================================================================
__global__ __launch_bounds__(256) void rmsnorm_kernel(
    const float* __restrict__ fused, const float* __restrict__ x,
    const float* __restrict__ w, float* __restrict__ out)
{
    const int t = blockIdx.x;
    const int tid = threadIdx.x;
    const float* fr = fused + (size_t)t * 1024;
    const float* xr = x + (size_t)t * 1024;
    float y[4];
    float ss = 0.f;
#pragma unroll
    for (int i = 0; i < 4; i++) {
        int c = tid + i * 256;
        y[i] = fr[c] + xr[c];
        ss += y[i] * y[i];
    }
#pragma unroll
    for (int off = 16; off >= 1; off >>= 1)
        ss += __shfl_xor_sync(0xffffffffu, ss, off);
    __shared__ float red[8];
    if ((tid & 31) == 0) red[tid >> 5] = ss;
    __syncthreads();
    float tot = red[0] + red[1] + red[2] + red[3] + red[4] + red[5] + red[6] + red[7];
    float r = rsqrtf(tot * (1.f / 1024.f) + 1e-6f);
    float* orow = out + (size_t)t * 1024;
#pragma unroll
    for (int i = 0; i < 4; i++) {
        int c = tid + i * 256;
        orow[c] = y[i] * r * w[c];
    }
}

// =================================================================================
// Launch
// =================================================================================
extern "C" void kernel_launch(void* const* d_in, const int* in_sizes, int n_in,
                              void* d_out, int out_size)
{
    const float* x       = (const float*)d_in[0];
    const float* w_qkv[4] = { (const float*)d_in[1], (const float*)d_in[3],
                              (const float*)d_in[5], (const float*)d_in[7] };
    const float* w_o[4]   = { (const float*)d_in[2], (const float*)d_in[4],
                              (const float*)d_in[6], (const float*)d_in[8] };
    const float* w_gate  = (const float*)d_in[9];
    const float* b_gate  = (const float*)d_in[10];
    const float* w_out   = (const float*)d_in[11];
    const float* norm_w  = (const float*)d_in[12];
    float* out = (float*)d_out;

    __nv_bfloat16 *xh, *xl, *wqkvh, *wqkvl, *woh, *wol, *wgh, *wgl, *wouth, *woutl;
    __nv_bfloat16 *qkvh, *qkvl, *attnh, *attnl, *conch, *concl, *gath, *gatl;
    float *fused;
    cudaGetSymbolAddress((void**)&xh, g_xh);       cudaGetSymbolAddress((void**)&xl, g_xl);
    cudaGetSymbolAddress((void**)&wqkvh, g_wqkvh); cudaGetSymbolAddress((void**)&wqkvl, g_wqkvl);
    cudaGetSymbolAddress((void**)&woh, g_woh);     cudaGetSymbolAddress((void**)&wol, g_wol);
    cudaGetSymbolAddress((void**)&wgh, g_wgh);     cudaGetSymbolAddress((void**)&wgl, g_wgl);
    cudaGetSymbolAddress((void**)&wouth, g_wouth); cudaGetSymbolAddress((void**)&woutl, g_woutl);
    cudaGetSymbolAddress((void**)&qkvh, g_qkvh);   cudaGetSymbolAddress((void**)&qkvl, g_qkvl);
    cudaGetSymbolAddress((void**)&attnh, g_attnh); cudaGetSymbolAddress((void**)&attnl, g_attnl);
    cudaGetSymbolAddress((void**)&conch, g_conch); cudaGetSymbolAddress((void**)&concl, g_concl);
    cudaGetSymbolAddress((void**)&gath, g_gath);   cudaGetSymbolAddress((void**)&gatl, g_gatl);
    cudaGetSymbolAddress((void**)&fused, g_fused);

    cudaFuncSetAttribute(attn_kernel, cudaFuncAttributeMaxDynamicSharedMemorySize, ATTN_SMEM);
    cudaFuncSetAttribute(gemm_bf16, cudaFuncAttributeMaxDynamicSharedMemorySize, GSMEM);

    convert_split<<<2048, 256>>>(x, xh, xl, NTOK * DMODEL);
    for (int d = 0; d < 4; d++) {
        convert_split<<<2048, 256>>>(w_qkv[d], wqkvh + (size_t)d * 3072 * 1024,
                                     wqkvl + (size_t)d * 3072 * 1024, 3072 * 1024);
        convert_split<<<2048, 256>>>(w_o[d], woh + (size_t)d * 1024 * 1024,
                                     wol + (size_t)d * 1024 * 1024, 1024 * 1024);
    }
    convert_split<<<4096, 256>>>(w_gate, wgh, wgl, 4096 * 4096);
    convert_split<<<2048, 256>>>(w_out, wouth, woutl, 1024 * 4096);

    for (int dir = 0; dir < 4; dir++) {
        const int tr  = (dir >= 2) ? 1 : 0;
        const int rev = (dir & 1);

        // QKV: x @ w_qkv^T -> qkv (bf16 hi/lo)
        gemm_bf16<<<dim3(3072 / 128, 4096 / 128), 256, GSMEM>>>(
            xh, xl, wqkvh + (size_t)dir * 3072 * 1024, wqkvl + (size_t)dir * 3072 * 1024,
            1024, 1, nullptr, qkvh, qkvl, nullptr, nullptr, nullptr, 3072, 0);

        attn_kernel<<<dim3(16, 4 * NH), 128, ATTN_SMEM>>>(qkvh, qkvl, attnh, attnl, tr, rev);

        // O-proj -> concat block (bf16 hi/lo)
        gemm_bf16<<<dim3(1024 / 128, 4096 / 128), 256, GSMEM>>>(
            attnh, attnl, woh + (size_t)dir * 1024 * 1024, wol + (size_t)dir * 1024 * 1024,
            1024, 1, nullptr, conch, concl, nullptr, nullptr, nullptr, 4096, dir * 1024);
    }

    // gate: sigmoid(concat @ w_gate^T + b) * concat -> gated
    gemm_bf16<<<dim3(4096 / 128, 4096 / 128), 256, GSMEM>>>(
        conch, concl, wgh, wgl, 4096, 2, nullptr, gath, gatl, b_gate, conch, concl, 4096, 0);

    // out: gated @ w_out^T -> fused fp32
    gemm_bf16<<<dim3(1024 / 128, 4096 / 128), 256, GSMEM>>>(
        gath, gatl, wouth, woutl, 4096, 0, fused, nullptr, nullptr, nullptr, nullptr, nullptr, 1024, 0);

    rmsnorm_kernel<<<NTOK, 256>>>(fused, x, norm_w, out);
}

// round 6
// speedup vs baseline: 1.7830x; 1.0941x over previous
#include <cuda_runtime.h>
#include <cuda_bf16.h>
#include <math.h>
#include <stdint.h>

#define NTOK 4096
#define DMODEL 1024
#define NH 16
#define TSEQ 1024

// ---------------- helpers ----------------
__device__ __forceinline__ uint32_t smem_u32(const void* p) {
    uint32_t a;
    asm("{ .reg .u64 t; cvta.to.shared.u64 t, %1; cvt.u32.u64 %0, t; }" : "=r"(a) : "l"(p));
    return a;
}

#define LDSM4(r, addr) \
    asm volatile("ldmatrix.sync.aligned.m8n8.x4.shared.b16 {%0,%1,%2,%3}, [%4];" \
        : "=r"((r)[0]), "=r"((r)[1]), "=r"((r)[2]), "=r"((r)[3]) : "r"(addr))

#define LDSM4T(r, addr) \
    asm volatile("ldmatrix.sync.aligned.m8n8.x4.trans.shared.b16 {%0,%1,%2,%3}, [%4];" \
        : "=r"((r)[0]), "=r"((r)[1]), "=r"((r)[2]), "=r"((r)[3]) : "r"(addr))

#define MMA(c, a, b) \
    asm volatile("mma.sync.aligned.m16n8k16.row.col.f32.bf16.bf16.f32 " \
        "{%0,%1,%2,%3}, {%4,%5,%6,%7}, {%8,%9}, {%0,%1,%2,%3};" \
        : "+f"((c)[0]), "+f"((c)[1]), "+f"((c)[2]), "+f"((c)[3]) \
        : "r"((a)[0]), "r"((a)[1]), "r"((a)[2]), "r"((a)[3]), "r"((b)[0]), "r"((b)[1]))

#define CP_ASYNC16(dst, src) \
    asm volatile("cp.async.cg.shared.global [%0], [%1], 16;" :: "r"(dst), "l"(src) : "memory")
#define CP_COMMIT() asm volatile("cp.async.commit_group;" ::: "memory")
#define CP_WAIT0()  asm volatile("cp.async.wait_group 0;" ::: "memory")
#define CP_WAIT1()  asm volatile("cp.async.wait_group 1;" ::: "memory")

// ---------------- scratch (device globals) ----------------
__device__ __align__(256) __nv_bfloat16 g_xh[(size_t)NTOK * DMODEL];
__device__ __align__(256) __nv_bfloat16 g_xl[(size_t)NTOK * DMODEL];
__device__ __align__(256) __nv_bfloat16 g_wqkvh[(size_t)4 * 3072 * 1024];
__device__ __align__(256) __nv_bfloat16 g_wqkvl[(size_t)4 * 3072 * 1024];
__device__ __align__(256) __nv_bfloat16 g_woh[(size_t)4 * 1024 * 1024];
__device__ __align__(256) __nv_bfloat16 g_wol[(size_t)4 * 1024 * 1024];
__device__ __align__(256) __nv_bfloat16 g_wgh[(size_t)4096 * 4096];
__device__ __align__(256) __nv_bfloat16 g_wgl[(size_t)4096 * 4096];
__device__ __align__(256) __nv_bfloat16 g_wouth[(size_t)1024 * 4096];
__device__ __align__(256) __nv_bfloat16 g_woutl[(size_t)1024 * 4096];
__device__ __align__(256) __nv_bfloat16 g_qkvh[(size_t)4 * NTOK * 3072];
__device__ __align__(256) __nv_bfloat16 g_qkvl[(size_t)4 * NTOK * 3072];
__device__ __align__(256) __nv_bfloat16 g_attnh[(size_t)4 * NTOK * 1024];
__device__ __align__(256) __nv_bfloat16 g_attnl[(size_t)4 * NTOK * 1024];
__device__ __align__(256) __nv_bfloat16 g_conch[(size_t)NTOK * 4096];
__device__ __align__(256) __nv_bfloat16 g_concl[(size_t)NTOK * 4096];
__device__ __align__(256) __nv_bfloat16 g_gath[(size_t)NTOK * 4096];
__device__ __align__(256) __nv_bfloat16 g_gatl[(size_t)NTOK * 4096];
__device__ __align__(256) float g_fused[(size_t)NTOK * 1024];

// ---------------- fp32 -> bf16 hi/lo split (vectorized x4) ----------------
__global__ __launch_bounds__(256) void convert_split(
    const float* __restrict__ in, __nv_bfloat16* __restrict__ h,
    __nv_bfloat16* __restrict__ l, int n)
{
    const int n4 = n >> 2;
    for (int i = blockIdx.x * 256 + threadIdx.x; i < n4; i += gridDim.x * 256) {
        float4 v = ((const float4*)in)[i];
        __nv_bfloat16 h0 = __float2bfloat16(v.x), h1 = __float2bfloat16(v.y);
        __nv_bfloat16 h2 = __float2bfloat16(v.z), h3 = __float2bfloat16(v.w);
        __nv_bfloat16 l0 = __float2bfloat16(v.x - __bfloat162float(h0));
        __nv_bfloat16 l1 = __float2bfloat16(v.y - __bfloat162float(h1));
        __nv_bfloat16 l2 = __float2bfloat16(v.z - __bfloat162float(h2));
        __nv_bfloat16 l3 = __float2bfloat16(v.w - __bfloat162float(h3));
        __nv_bfloat162 hp[2], lp[2];
        hp[0].x = h0; hp[0].y = h1; hp[1].x = h2; hp[1].y = h3;
        lp[0].x = l0; lp[0].y = l1; lp[1].x = l2; lp[1].y = l3;
        ((uint2*)h)[i] = *(uint2*)hp;
        ((uint2*)l)[i] = *(uint2*)lp;
    }
}

// =================================================================================
// HMMA bf16 3-term split GEMM: CTA 128x128, K-step 32, 3-stage cp.async (96KB),
// one barrier per chunk. Batched over blockIdx.z via sA/sB/sCoff strides.
// mode 0: Cf = acc; mode 1: (Ch,Cl)=split(acc); mode 2: sigmoid-gate epilogue
// =================================================================================
#define STAGEB 32768
#define GSMEM  (3 * STAGEB)

__device__ __forceinline__ void load_stage(
    const __nv_bfloat16* __restrict__ Ah, const __nv_bfloat16* __restrict__ Al,
    const __nv_bfloat16* __restrict__ Bh, const __nv_bfloat16* __restrict__ Bl,
    int K, int k0, int bm, int bn, uint32_t sstage, int tid)
{
#pragma unroll
    for (int it = 0; it < 8; it++) {
        int cidx = tid + it * 256;
        int t = cidx >> 9;
        int row = (cidx >> 2) & 127;
        int c = cidx & 3;
        const __nv_bfloat16* src = (t == 0) ? Ah : (t == 1) ? Al : (t == 2) ? Bh : Bl;
        int rb = (t < 2) ? bm : bn;
        const __nv_bfloat16* gsrc = src + (size_t)(rb + row) * K + k0 + c * 8;
        uint32_t dst = sstage + t * 8192 + row * 64 + ((c ^ ((row >> 1) & 3)) << 4);
        CP_ASYNC16(dst, gsrc);
    }
    CP_COMMIT();
}

__global__ __launch_bounds__(256, 2) void gemm_bf16(
    const __nv_bfloat16* __restrict__ Ah, const __nv_bfloat16* __restrict__ Al,
    const __nv_bfloat16* __restrict__ Bh, const __nv_bfloat16* __restrict__ Bl,
    int K, int mode,
    float* __restrict__ Cf,
    __nv_bfloat16* __restrict__ Ch, __nv_bfloat16* __restrict__ Cl,
    const float* __restrict__ bias,
    const __nv_bfloat16* __restrict__ Xh, const __nv_bfloat16* __restrict__ Xl,
    int ldc, int coff, size_t sA, size_t sB, int sCoff)
{
    extern __shared__ char smem[];
    const uint32_t sb = smem_u32(smem);
    const int tid = threadIdx.x;
    const int wid = tid >> 5, lane = tid & 31;
    const int bm = blockIdx.y * 128;
    const int bn = blockIdx.x * 128;
    const int z = blockIdx.z;
    Ah += (size_t)z * sA; Al += (size_t)z * sA;
    Bh += (size_t)z * sB; Bl += (size_t)z * sB;
    coff += z * sCoff;
    const int wm = (wid >> 2) * 64;
    const int wn = (wid & 3) * 32;

    float acc[4][4][4];
#pragma unroll
    for (int mi = 0; mi < 4; mi++)
#pragma unroll
        for (int nj = 0; nj < 4; nj++)
#pragma unroll
            for (int q = 0; q < 4; q++) acc[mi][nj][q] = 0.f;

    const int nchunk = K >> 5;
    load_stage(Ah, Al, Bh, Bl, K, 0, bm, bn, sb, tid);
    load_stage(Ah, Al, Bh, Bl, K, 32, bm, bn, sb + STAGEB, tid);

    int slot = 0;
    for (int i = 0; i < nchunk; i++) {
        if (i + 1 < nchunk) CP_WAIT1(); else CP_WAIT0();
        __syncthreads();
        if (i + 2 < nchunk) {
            int ns = slot + 2; if (ns >= 3) ns -= 3;
            load_stage(Ah, Al, Bh, Bl, K, (i + 2) << 5, bm, bn, sb + ns * STAGEB, tid);
        }

        const uint32_t st = sb + slot * STAGEB;
#pragma unroll
        for (int ks = 0; ks < 2; ks++) {
            uint32_t ah[4][4], al[4][4], bh[2][4], bl[2][4];
#pragma unroll
            for (int mi = 0; mi < 4; mi++) {
                int row = wm + mi * 16 + (lane & 15);
                int ch = (lane >> 4) + ks * 2;
                uint32_t ad = st + row * 64 + ((ch ^ ((row >> 1) & 3)) << 4);
                LDSM4(ah[mi], ad);
                LDSM4(al[mi], ad + 8192);
            }
#pragma unroll
            for (int nb = 0; nb < 2; nb++) {
                int row = wn + nb * 16 + (lane & 7) + ((lane >> 4) << 3);
                int ch = ((lane >> 3) & 1) + ks * 2;
                uint32_t ad = st + 16384 + row * 64 + ((ch ^ ((row >> 1) & 3)) << 4);
                LDSM4(bh[nb], ad);
                LDSM4(bl[nb], ad + 8192);
            }
#pragma unroll
            for (int mi = 0; mi < 4; mi++)
#pragma unroll
                for (int nj = 0; nj < 4; nj++) {
                    uint32_t* bhp = &bh[nj >> 1][(nj & 1) * 2];
                    uint32_t* blp = &bl[nj >> 1][(nj & 1) * 2];
                    MMA(acc[mi][nj], ah[mi], bhp);
                    MMA(acc[mi][nj], ah[mi], blp);
                    MMA(acc[mi][nj], al[mi], bhp);
                }
        }
        if (++slot >= 3) slot = 0;
    }

    // epilogue
#pragma unroll
    for (int mi = 0; mi < 4; mi++) {
#pragma unroll
        for (int r = 0; r < 2; r++) {
            int m = bm + wm + mi * 16 + (lane >> 2) + r * 8;
#pragma unroll
            for (int nj = 0; nj < 4; nj++) {
                int n = bn + wn + nj * 8 + (lane & 3) * 2;
                float v0 = acc[mi][nj][r * 2 + 0];
                float v1 = acc[mi][nj][r * 2 + 1];
                size_t o = (size_t)m * ldc + coff + n;
                if (mode == 0) {
                    *(float2*)(Cf + o) = make_float2(v0, v1);
                } else {
                    if (mode == 2) {
                        float g0 = 1.f / (1.f + __expf(-(v0 + bias[n])));
                        float g1 = 1.f / (1.f + __expf(-(v1 + bias[n + 1])));
                        float a0 = __bfloat162float(Xh[o]) + __bfloat162float(Xl[o]);
                        float a1 = __bfloat162float(Xh[o + 1]) + __bfloat162float(Xl[o + 1]);
                        v0 = g0 * a0; v1 = g1 * a1;
                    }
                    __nv_bfloat16 h0 = __float2bfloat16(v0);
                    __nv_bfloat16 h1 = __float2bfloat16(v1);
                    __nv_bfloat16 l0 = __float2bfloat16(v0 - __bfloat162float(h0));
                    __nv_bfloat16 l1 = __float2bfloat16(v1 - __bfloat162float(h1));
                    __nv_bfloat162 hp; hp.x = h0; hp.y = h1;
                    __nv_bfloat162 lp; lp.x = l0; lp.y = l1;
                    *(__nv_bfloat162*)(Ch + o) = hp;
                    *(__nv_bfloat162*)(Cl + o) = lp;
                }
            }
        }
    }
}

// =================================================================================
// Flash attention, HMMA bf16 3-term split. All 4 directions via blockIdx.z.
// =================================================================================
#define ATTN_SMEM 65536

__global__ __launch_bounds__(128) void attn_kernel(
    const __nv_bfloat16* __restrict__ qkvh, const __nv_bfloat16* __restrict__ qkvl,
    __nv_bfloat16* __restrict__ attnh, __nv_bfloat16* __restrict__ attnl)
{
    extern __shared__ char smem[];
    const uint32_t sb = smem_u32(smem);
    const int dir = blockIdx.z;
    const int tr = dir >= 2, rev = dir & 1;
    qkvh += (size_t)dir * NTOK * 3072;
    qkvl += (size_t)dir * NTOK * 3072;
    attnh += (size_t)dir * NTOK * 1024;
    attnl += (size_t)dir * NTOK * 1024;
    const int qt = blockIdx.x;
    const int b  = blockIdx.y >> 4;
    const int h  = blockIdx.y & 15;
    const int tid = threadIdx.x;
    const int wid = tid >> 5, lane = tid & 31;
    const size_t bq = (size_t)b * TSEQ;
    const uint32_t sQh = sb, sQl = sb + 8192, sKh = sb + 16384, sKl = sb + 24576;
    const uint32_t sVh = sb + 32768, sVl = sb + 40960, sPh = sb + 49152, sPl = sb + 57344;

    {
        const __nv_bfloat162 s2 = __float2bfloat162_rn(0.125f);
        for (int i = tid; i < 1024; i += 128) {
            int half = i >> 9;
            int j = i & 511;
            int row = j >> 3, c = j & 7;
            int t = qt * 64 + row;
            int tok = tr ? ((t & 31) * 32 + (t >> 5)) : t;
            const __nv_bfloat16* src = (half ? qkvl : qkvh) + (bq + tok) * 3072 + h * 64 + c * 8;
            uint4 v = *(const uint4*)src;
            __nv_bfloat162* p2 = (__nv_bfloat162*)&v;
#pragma unroll
            for (int q = 0; q < 4; q++) p2[q] = __hmul2(p2[q], s2);
            uint32_t off = half * 8192 + row * 128 + ((c ^ (row & 7)) << 4);
            *(uint4*)(smem + off) = v;
        }
    }

    float m0[2] = {-1e30f, -1e30f}, l0[2] = {0.f, 0.f};
    float o[8][4];
#pragma unroll
    for (int nj = 0; nj < 8; nj++)
#pragma unroll
        for (int q = 0; q < 4; q++) o[nj][q] = 0.f;

    const int kt_lo = rev ? qt : 0;
    const int kt_hi = rev ? 15 : qt;

    for (int kt = kt_lo; kt <= kt_hi; kt++) {
        __syncthreads();
        for (int i = tid; i < 2048; i += 128) {
            int arr = i >> 9;
            int j = i & 511;
            int row = j >> 3, c = j & 7;
            int t = kt * 64 + row;
            int tok = tr ? ((t & 31) * 32 + (t >> 5)) : t;
            const __nv_bfloat16* src = ((arr & 1) ? qkvl : qkvh)
                + (bq + tok) * 3072 + 1024 + (arr >> 1) * 1024 + h * 64 + c * 8;
            uint32_t dst = sKh + arr * 8192 + row * 128 + ((c ^ (row & 7)) << 4);
            CP_ASYNC16(dst, src);
        }
        CP_COMMIT(); CP_WAIT0();
        __syncthreads();

        float s[8][4];
#pragma unroll
        for (int nj = 0; nj < 8; nj++)
#pragma unroll
            for (int q = 0; q < 4; q++) s[nj][q] = 0.f;
#pragma unroll
        for (int kk = 0; kk < 4; kk++) {
            uint32_t qh_f[4], ql_f[4];
            {
                int row = wid * 16 + (lane & 15);
                int ch = (lane >> 4) + kk * 2;
                uint32_t ad = row * 128 + ((ch ^ (row & 7)) << 4);
                LDSM4(qh_f, sQh + ad);
                LDSM4(ql_f, sQl + ad);
            }
#pragma unroll
            for (int nb = 0; nb < 4; nb++) {
                uint32_t kh_f[4], kl_f[4];
                int row = nb * 16 + (lane & 7) + ((lane >> 4) << 3);
                int ch = ((lane >> 3) & 1) + kk * 2;
                uint32_t ad = row * 128 + ((ch ^ (row & 7)) << 4);
                LDSM4(kh_f, sKh + ad);
                LDSM4(kl_f, sKl + ad);
#pragma unroll
                for (int half = 0; half < 2; half++) {
                    int nj = nb * 2 + half;
                    uint32_t* bhp = &kh_f[half * 2];
                    uint32_t* blp = &kl_f[half * 2];
                    MMA(s[nj], qh_f, bhp);
                    MMA(s[nj], qh_f, blp);
                    MMA(s[nj], ql_f, bhp);
                }
            }
        }

        if (kt == qt) {
#pragma unroll
            for (int nj = 0; nj < 8; nj++)
#pragma unroll
                for (int q = 0; q < 4; q++) {
                    int rr = q >> 1;
                    int qi = qt * 64 + wid * 16 + (lane >> 2) + rr * 8;
                    int ki = kt * 64 + nj * 8 + (lane & 3) * 2 + (q & 1);
                    bool valid = rev ? (ki >= qi) : (ki <= qi);
                    if (!valid) s[nj][q] = -1e30f;
                }
        }

#pragma unroll
        for (int rr = 0; rr < 2; rr++) {
            float vm = -1e30f;
#pragma unroll
            for (int nj = 0; nj < 8; nj++) {
                vm = fmaxf(vm, s[nj][rr * 2 + 0]);
                vm = fmaxf(vm, s[nj][rr * 2 + 1]);
            }
            vm = fmaxf(vm, __shfl_xor_sync(0xffffffffu, vm, 1));
            vm = fmaxf(vm, __shfl_xor_sync(0xffffffffu, vm, 2));
            float mn = fmaxf(m0[rr], vm);
            float fac = __expf(m0[rr] - mn);
            float rs = 0.f;
            int qrow = wid * 16 + (lane >> 2) + rr * 8;
#pragma unroll
            for (int nj = 0; nj < 8; nj++) {
                float p0 = __expf(s[nj][rr * 2 + 0] - mn);
                float p1 = __expf(s[nj][rr * 2 + 1] - mn);
                rs += p0 + p1;
                __nv_bfloat16 h0 = __float2bfloat16(p0);
                __nv_bfloat16 h1 = __float2bfloat16(p1);
                __nv_bfloat16 e0 = __float2bfloat16(p0 - __bfloat162float(h0));
                __nv_bfloat16 e1 = __float2bfloat16(p1 - __bfloat162float(h1));
                uint32_t off = qrow * 128 + ((nj ^ (qrow & 7)) << 4) + (lane & 3) * 4;
                __nv_bfloat162 hp; hp.x = h0; hp.y = h1;
                __nv_bfloat162 lp; lp.x = e0; lp.y = e1;
                *(__nv_bfloat162*)(smem + (sPh - sb) + off) = hp;
                *(__nv_bfloat162*)(smem + (sPl - sb) + off) = lp;
            }
            rs += __shfl_xor_sync(0xffffffffu, rs, 1);
            rs += __shfl_xor_sync(0xffffffffu, rs, 2);
            l0[rr] = l0[rr] * fac + rs;
            m0[rr] = mn;
#pragma unroll
            for (int nj = 0; nj < 8; nj++) {
                o[nj][rr * 2 + 0] *= fac;
                o[nj][rr * 2 + 1] *= fac;
            }
        }

#pragma unroll
        for (int kk = 0; kk < 4; kk++) {
            uint32_t ph_f[4], pl_f[4];
            {
                int row = wid * 16 + (lane & 15);
                int ch = (lane >> 4) + kk * 2;
                uint32_t ad = row * 128 + ((ch ^ (row & 7)) << 4);
                LDSM4(ph_f, sPh + ad);
                LDSM4(pl_f, sPl + ad);
            }
#pragma unroll
            for (int nb = 0; nb < 4; nb++) {
                uint32_t vh_f[4], vl_f[4];
                int row = kk * 16 + (lane & 15);
                int ch = (nb * 2 + (lane >> 4)) ^ (row & 7);
                uint32_t ad = row * 128 + (ch << 4);
                LDSM4T(vh_f, sVh + ad);
                LDSM4T(vl_f, sVl + ad);
#pragma unroll
                for (int half = 0; half < 2; half++) {
                    int nj = nb * 2 + half;
                    uint32_t* bhp = &vh_f[half * 2];
                    uint32_t* blp = &vl_f[half * 2];
                    MMA(o[nj], ph_f, bhp);
                    MMA(o[nj], ph_f, blp);
                    MMA(o[nj], pl_f, bhp);
                }
            }
        }
    }

#pragma unroll
    for (int rr = 0; rr < 2; rr++) {
        float inv = 1.f / l0[rr];
        int qrow = wid * 16 + (lane >> 2) + rr * 8;
        int t = qt * 64 + qrow;
        int tok = tr ? ((t & 31) * 32 + (t >> 5)) : t;
        size_t base = (bq + tok) * 1024 + h * 64;
#pragma unroll
        for (int nj = 0; nj < 8; nj++) {
            int d = nj * 8 + (lane & 3) * 2;
            float v0 = o[nj][rr * 2 + 0] * inv;
            float v1 = o[nj][rr * 2 + 1] * inv;
            __nv_bfloat16 h0 = __float2bfloat16(v0);
            __nv_bfloat16 h1 = __float2bfloat16(v1);
            __nv_bfloat16 e0 = __float2bfloat16(v0 - __bfloat162float(h0));
            __nv_bfloat16 e1 = __float2bfloat16(v1 - __bfloat162float(h1));
            __nv_bfloat162 hp; hp.x = h0; hp.y = h1;
            __nv_bfloat162 lp; lp.x = e0; lp.y = e1;
            *(__nv_bfloat162*)(attnh + base + d) = hp;
            *(__nv_bfloat162*)(attnl + base + d) = lp;
        }
    }
}

// =================================================================================
// RMSNorm epilogue
// =================================================================================
__global__ __launch_bounds__(256) void rmsnorm_kernel(
    const float* __restrict__ fused, const float* __restrict__ x,
    const float* __restrict__ w, float* __restrict__ out)
{
    const int t = blockIdx.x;
    const int tid = threadIdx.x;
    const float* fr = fused + (size_t)t * 1024;
    const float* xr = x + (size_t)t * 1024;
    float y[4];
    float ss = 0.f;
#pragma unroll
    for (int i = 0; i < 4; i++) {
        int c = tid + i * 256;
        y[i] = fr[c] + xr[c];
        ss += y[i] * y[i];
    }
#pragma unroll
    for (int off = 16; off >= 1; off >>= 1)
        ss += __shfl_xor_sync(0xffffffffu, ss, off);
    __shared__ float red[8];
    if ((tid & 31) == 0) red[tid >> 5] = ss;
    __syncthreads();
    float tot = red[0] + red[1] + red[2] + red[3] + red[4] + red[5] + red[6] + red[7];
    float r = rsqrtf(tot * (1.f / 1024.f) + 1e-6f);
    float* orow = out + (size_t)t * 1024;
#pragma unroll
    for (int i = 0; i < 4; i++) {
        int c = tid + i * 256;
        orow[c] = y[i] * r * w[c];
    }
}

// =================================================================================
// Launch
// =================================================================================
extern "C" void kernel_launch(void* const* d_in, const int* in_sizes, int n_in,
                              void* d_out, int out_size)
{
    const float* x       = (const float*)d_in[0];
    const float* w_qkv[4] = { (const float*)d_in[1], (const float*)d_in[3],
                              (const float*)d_in[5], (const float*)d_in[7] };
    const float* w_o[4]   = { (const float*)d_in[2], (const float*)d_in[4],
                              (const float*)d_in[6], (const float*)d_in[8] };
    const float* w_gate  = (const float*)d_in[9];
    const float* b_gate  = (const float*)d_in[10];
    const float* w_out   = (const float*)d_in[11];
    const float* norm_w  = (const float*)d_in[12];
    float* out = (float*)d_out;

    __nv_bfloat16 *xh, *xl, *wqkvh, *wqkvl, *woh, *wol, *wgh, *wgl, *wouth, *woutl;
    __nv_bfloat16 *qkvh, *qkvl, *attnh, *attnl, *conch, *concl, *gath, *gatl;
    float *fused;
    cudaGetSymbolAddress((void**)&xh, g_xh);       cudaGetSymbolAddress((void**)&xl, g_xl);
    cudaGetSymbolAddress((void**)&wqkvh, g_wqkvh); cudaGetSymbolAddress((void**)&wqkvl, g_wqkvl);
    cudaGetSymbolAddress((void**)&woh, g_woh);     cudaGetSymbolAddress((void**)&wol, g_wol);
    cudaGetSymbolAddress((void**)&wgh, g_wgh);     cudaGetSymbolAddress((void**)&wgl, g_wgl);
    cudaGetSymbolAddress((void**)&wouth, g_wouth); cudaGetSymbolAddress((void**)&woutl, g_woutl);
    cudaGetSymbolAddress((void**)&qkvh, g_qkvh);   cudaGetSymbolAddress((void**)&qkvl, g_qkvl);
    cudaGetSymbolAddress((void**)&attnh, g_attnh); cudaGetSymbolAddress((void**)&attnl, g_attnl);
    cudaGetSymbolAddress((void**)&conch, g_conch); cudaGetSymbolAddress((void**)&concl, g_concl);
    cudaGetSymbolAddress((void**)&gath, g_gath);   cudaGetSymbolAddress((void**)&gatl, g_gatl);
    cudaGetSymbolAddress((void**)&fused, g_fused);

    cudaFuncSetAttribute(attn_kernel, cudaFuncAttributeMaxDynamicSharedMemorySize, ATTN_SMEM);
    cudaFuncSetAttribute(gemm_bf16, cudaFuncAttributeMaxDynamicSharedMemorySize, GSMEM);

    // converts (vectorized)
    convert_split<<<1024, 256>>>(x, xh, xl, NTOK * DMODEL);
    for (int d = 0; d < 4; d++) {
        convert_split<<<2048, 256>>>(w_qkv[d], wqkvh + (size_t)d * 3072 * 1024,
                                     wqkvl + (size_t)d * 3072 * 1024, 3072 * 1024);
        convert_split<<<1024, 256>>>(w_o[d], woh + (size_t)d * 1024 * 1024,
                                     wol + (size_t)d * 1024 * 1024, 1024 * 1024);
    }
    convert_split<<<4096, 256>>>(w_gate, wgh, wgl, 4096 * 4096);
    convert_split<<<2048, 256>>>(w_out, wouth, woutl, 1024 * 4096);

    // QKV for all 4 directions
    for (int dir = 0; dir < 4; dir++) {
        gemm_bf16<<<dim3(3072 / 128, 4096 / 128), 256, GSMEM>>>(
            xh, xl, wqkvh + (size_t)dir * 3072 * 1024, wqkvl + (size_t)dir * 3072 * 1024,
            1024, 1, nullptr,
            qkvh + (size_t)dir * NTOK * 3072, qkvl + (size_t)dir * NTOK * 3072,
            nullptr, nullptr, nullptr, 3072, 0, 0, 0, 0);
    }

    // attention, all directions in one launch
    attn_kernel<<<dim3(16, 4 * NH, 4), 128, ATTN_SMEM>>>(qkvh, qkvl, attnh, attnl);

    // O-proj, batched over directions
    gemm_bf16<<<dim3(1024 / 128, 4096 / 128, 4), 256, GSMEM>>>(
        attnh, attnl, woh, wol,
        1024, 1, nullptr, conch, concl, nullptr, nullptr, nullptr,
        4096, 0, (size_t)NTOK * 1024, (size_t)1024 * 1024, 1024);

    // gate: sigmoid(concat @ w_gate^T + b) * concat -> gated
    gemm_bf16<<<dim3(4096 / 128, 4096 / 128), 256, GSMEM>>>(
        conch, concl, wgh, wgl, 4096, 2, nullptr, gath, gatl, b_gate, conch, concl,
        4096, 0, 0, 0, 0);

    // out: gated @ w_out^T -> fused fp32
    gemm_bf16<<<dim3(1024 / 128, 4096 / 128), 256, GSMEM>>>(
        gath, gatl, wouth, woutl, 4096, 0, fused, nullptr, nullptr, nullptr, nullptr, nullptr,
        1024, 0, 0, 0, 0);

    rmsnorm_kernel<<<NTOK, 256>>>(fused, x, norm_w, out);
}

// round 7
// speedup vs baseline: 2.3947x; 1.3431x over previous
#include <cuda_runtime.h>
#include <cuda_bf16.h>
#include <cuda_fp16.h>
#include <math.h>
#include <stdint.h>

#define NTOK 4096
#define DMODEL 1024
#define NH 16
#define TSEQ 1024

// ---------------- helpers ----------------
__device__ __forceinline__ uint32_t smem_u32(const void* p) {
    uint32_t a;
    asm("{ .reg .u64 t; cvta.to.shared.u64 t, %1; cvt.u32.u64 %0, t; }" : "=r"(a) : "l"(p));
    return a;
}

#define LDSM4(r, addr) \
    asm volatile("ldmatrix.sync.aligned.m8n8.x4.shared.b16 {%0,%1,%2,%3}, [%4];" \
        : "=r"((r)[0]), "=r"((r)[1]), "=r"((r)[2]), "=r"((r)[3]) : "r"(addr))

#define LDSM4T(r, addr) \
    asm volatile("ldmatrix.sync.aligned.m8n8.x4.trans.shared.b16 {%0,%1,%2,%3}, [%4];" \
        : "=r"((r)[0]), "=r"((r)[1]), "=r"((r)[2]), "=r"((r)[3]) : "r"(addr))

#define MMA(c, a, b) \
    asm volatile("mma.sync.aligned.m16n8k16.row.col.f32.bf16.bf16.f32 " \
        "{%0,%1,%2,%3}, {%4,%5,%6,%7}, {%8,%9}, {%0,%1,%2,%3};" \
        : "+f"((c)[0]), "+f"((c)[1]), "+f"((c)[2]), "+f"((c)[3]) \
        : "r"((a)[0]), "r"((a)[1]), "r"((a)[2]), "r"((a)[3]), "r"((b)[0]), "r"((b)[1]))

#define MMAH(c, a, b) \
    asm volatile("mma.sync.aligned.m16n8k16.row.col.f32.f16.f16.f32 " \
        "{%0,%1,%2,%3}, {%4,%5,%6,%7}, {%8,%9}, {%0,%1,%2,%3};" \
        : "+f"((c)[0]), "+f"((c)[1]), "+f"((c)[2]), "+f"((c)[3]) \
        : "r"((a)[0]), "r"((a)[1]), "r"((a)[2]), "r"((a)[3]), "r"((b)[0]), "r"((b)[1]))

#define CP_ASYNC16(dst, src) \
    asm volatile("cp.async.cg.shared.global [%0], [%1], 16;" :: "r"(dst), "l"(src) : "memory")
#define CP_COMMIT() asm volatile("cp.async.commit_group;" ::: "memory")
#define CP_WAIT0()  asm volatile("cp.async.wait_group 0;" ::: "memory")
#define CP_WAIT1()  asm volatile("cp.async.wait_group 1;" ::: "memory")

// ---------------- scratch (device globals) ----------------
__device__ __align__(256) __nv_bfloat16 g_xh[(size_t)NTOK * DMODEL];
__device__ __align__(256) __nv_bfloat16 g_xl[(size_t)NTOK * DMODEL];
__device__ __align__(256) __nv_bfloat16 g_wqkvh[(size_t)4 * 3072 * 1024];
__device__ __align__(256) __nv_bfloat16 g_wqkvl[(size_t)4 * 3072 * 1024];
__device__ __align__(256) __nv_bfloat16 g_woh[(size_t)4 * 1024 * 1024];
__device__ __align__(256) __nv_bfloat16 g_wol[(size_t)4 * 1024 * 1024];
__device__ __align__(256) __half g_wg16[(size_t)4096 * 4096];
__device__ __align__(256) __half g_wout16[(size_t)1024 * 4096];
__device__ __align__(256) __nv_bfloat16 g_qkvh[(size_t)4 * NTOK * 3072];
__device__ __align__(256) __nv_bfloat16 g_qkvl[(size_t)4 * NTOK * 3072];
__device__ __align__(256) __nv_bfloat16 g_attnh[(size_t)4 * NTOK * 1024];
__device__ __align__(256) __nv_bfloat16 g_attnl[(size_t)4 * NTOK * 1024];
__device__ __align__(256) __nv_bfloat16 g_conch[(size_t)NTOK * 4096];
__device__ __align__(256) __nv_bfloat16 g_concl[(size_t)NTOK * 4096];
__device__ __align__(256) __half g_conc16[(size_t)NTOK * 4096];
__device__ __align__(256) __half g_gat16[(size_t)NTOK * 4096];
__device__ __align__(256) float g_fused[(size_t)NTOK * 1024];

// ---------------- fp32 -> bf16 hi/lo split (vectorized) ----------------
__global__ __launch_bounds__(256) void convert_split(
    const float* __restrict__ in, __nv_bfloat16* __restrict__ h,
    __nv_bfloat16* __restrict__ l, int n)
{
    const int n4 = n >> 2;
    for (int i = blockIdx.x * 256 + threadIdx.x; i < n4; i += gridDim.x * 256) {
        float4 v = ((const float4*)in)[i];
        __nv_bfloat16 h0 = __float2bfloat16(v.x), h1 = __float2bfloat16(v.y);
        __nv_bfloat16 h2 = __float2bfloat16(v.z), h3 = __float2bfloat16(v.w);
        __nv_bfloat16 l0 = __float2bfloat16(v.x - __bfloat162float(h0));
        __nv_bfloat16 l1 = __float2bfloat16(v.y - __bfloat162float(h1));
        __nv_bfloat16 l2 = __float2bfloat16(v.z - __bfloat162float(h2));
        __nv_bfloat16 l3 = __float2bfloat16(v.w - __bfloat162float(h3));
        __nv_bfloat162 hp[2], lp[2];
        hp[0].x = h0; hp[0].y = h1; hp[1].x = h2; hp[1].y = h3;
        lp[0].x = l0; lp[0].y = l1; lp[1].x = l2; lp[1].y = l3;
        ((uint2*)h)[i] = *(uint2*)hp;
        ((uint2*)l)[i] = *(uint2*)lp;
    }
}

// ---------------- fp32 -> fp16 (vectorized) ----------------
__global__ __launch_bounds__(256) void convert_fp16(
    const float* __restrict__ in, __half* __restrict__ o, int n)
{
    const int n4 = n >> 2;
    for (int i = blockIdx.x * 256 + threadIdx.x; i < n4; i += gridDim.x * 256) {
        float4 v = ((const float4*)in)[i];
        __half2 p[2];
        p[0] = __floats2half2_rn(v.x, v.y);
        p[1] = __floats2half2_rn(v.z, v.w);
        ((uint2*)o)[i] = *(uint2*)p;
    }
}

// =================================================================================
// HMMA bf16 3-term split GEMM: CTA 128x128, K-step 32, 3-stage cp.async (96KB).
// mode 1: (Ch,Cl)=split(acc);  mode 3: split(acc) + C16=fp16(acc)
// Batched over blockIdx.z via sA/sB/sCoff strides.
// =================================================================================
#define STAGEB 32768
#define GSMEM  (3 * STAGEB)

__device__ __forceinline__ void load_stage(
    const __nv_bfloat16* __restrict__ Ah, const __nv_bfloat16* __restrict__ Al,
    const __nv_bfloat16* __restrict__ Bh, const __nv_bfloat16* __restrict__ Bl,
    int K, int k0, int bm, int bn, uint32_t sstage, int tid)
{
#pragma unroll
    for (int it = 0; it < 8; it++) {
        int cidx = tid + it * 256;
        int t = cidx >> 9;
        int row = (cidx >> 2) & 127;
        int c = cidx & 3;
        const __nv_bfloat16* src = (t == 0) ? Ah : (t == 1) ? Al : (t == 2) ? Bh : Bl;
        int rb = (t < 2) ? bm : bn;
        const __nv_bfloat16* gsrc = src + (size_t)(rb + row) * K + k0 + c * 8;
        uint32_t dst = sstage + t * 8192 + row * 64 + ((c ^ ((row >> 1) & 3)) << 4);
        CP_ASYNC16(dst, gsrc);
    }
    CP_COMMIT();
}

__global__ __launch_bounds__(256, 2) void gemm_bf16(
    const __nv_bfloat16* __restrict__ Ah, const __nv_bfloat16* __restrict__ Al,
    const __nv_bfloat16* __restrict__ Bh, const __nv_bfloat16* __restrict__ Bl,
    int K, int mode,
    __nv_bfloat16* __restrict__ Ch, __nv_bfloat16* __restrict__ Cl,
    __half* __restrict__ C16,
    int ldc, int coff, size_t sA, size_t sB, int sCoff)
{
    extern __shared__ char smem[];
    const uint32_t sb = smem_u32(smem);
    const int tid = threadIdx.x;
    const int wid = tid >> 5, lane = tid & 31;
    const int bm = blockIdx.y * 128;
    const int bn = blockIdx.x * 128;
    const int z = blockIdx.z;
    Ah += (size_t)z * sA; Al += (size_t)z * sA;
    Bh += (size_t)z * sB; Bl += (size_t)z * sB;
    coff += z * sCoff;
    const int wm = (wid >> 2) * 64;
    const int wn = (wid & 3) * 32;

    float acc[4][4][4];
#pragma unroll
    for (int mi = 0; mi < 4; mi++)
#pragma unroll
        for (int nj = 0; nj < 4; nj++)
#pragma unroll
            for (int q = 0; q < 4; q++) acc[mi][nj][q] = 0.f;

    const int nchunk = K >> 5;
    load_stage(Ah, Al, Bh, Bl, K, 0, bm, bn, sb, tid);
    load_stage(Ah, Al, Bh, Bl, K, 32, bm, bn, sb + STAGEB, tid);

    int slot = 0;
    for (int i = 0; i < nchunk; i++) {
        if (i + 1 < nchunk) CP_WAIT1(); else CP_WAIT0();
        __syncthreads();
        if (i + 2 < nchunk) {
            int ns = slot + 2; if (ns >= 3) ns -= 3;
            load_stage(Ah, Al, Bh, Bl, K, (i + 2) << 5, bm, bn, sb + ns * STAGEB, tid);
        }

        const uint32_t st = sb + slot * STAGEB;
#pragma unroll
        for (int ks = 0; ks < 2; ks++) {
            uint32_t ah[4][4], al[4][4], bh[2][4], bl[2][4];
#pragma unroll
            for (int mi = 0; mi < 4; mi++) {
                int row = wm + mi * 16 + (lane & 15);
                int ch = (lane >> 4) + ks * 2;
                uint32_t ad = st + row * 64 + ((ch ^ ((row >> 1) & 3)) << 4);
                LDSM4(ah[mi], ad);
                LDSM4(al[mi], ad + 8192);
            }
#pragma unroll
            for (int nb = 0; nb < 2; nb++) {
                int row = wn + nb * 16 + (lane & 7) + ((lane >> 4) << 3);
                int ch = ((lane >> 3) & 1) + ks * 2;
                uint32_t ad = st + 16384 + row * 64 + ((ch ^ ((row >> 1) & 3)) << 4);
                LDSM4(bh[nb], ad);
                LDSM4(bl[nb], ad + 8192);
            }
#pragma unroll
            for (int mi = 0; mi < 4; mi++)
#pragma unroll
                for (int nj = 0; nj < 4; nj++) {
                    uint32_t* bhp = &bh[nj >> 1][(nj & 1) * 2];
                    uint32_t* blp = &bl[nj >> 1][(nj & 1) * 2];
                    MMA(acc[mi][nj], ah[mi], bhp);
                    MMA(acc[mi][nj], ah[mi], blp);
                    MMA(acc[mi][nj], al[mi], bhp);
                }
        }
        if (++slot >= 3) slot = 0;
    }

    // epilogue: bf16 split (+ optional fp16 copy)
#pragma unroll
    for (int mi = 0; mi < 4; mi++) {
#pragma unroll
        for (int r = 0; r < 2; r++) {
            int m = bm + wm + mi * 16 + (lane >> 2) + r * 8;
#pragma unroll
            for (int nj = 0; nj < 4; nj++) {
                int n = bn + wn + nj * 8 + (lane & 3) * 2;
                float v0 = acc[mi][nj][r * 2 + 0];
                float v1 = acc[mi][nj][r * 2 + 1];
                size_t o = (size_t)m * ldc + coff + n;
                __nv_bfloat16 h0 = __float2bfloat16(v0);
                __nv_bfloat16 h1 = __float2bfloat16(v1);
                __nv_bfloat16 l0 = __float2bfloat16(v0 - __bfloat162float(h0));
                __nv_bfloat16 l1 = __float2bfloat16(v1 - __bfloat162float(h1));
                __nv_bfloat162 hp; hp.x = h0; hp.y = h1;
                __nv_bfloat162 lp; lp.x = l0; lp.y = l1;
                *(__nv_bfloat162*)(Ch + o) = hp;
                *(__nv_bfloat162*)(Cl + o) = lp;
                if (mode == 3)
                    *(__half2*)(C16 + o) = __floats2half2_rn(v0, v1);
            }
        }
    }
}

// =================================================================================
// HMMA fp16 single-term GEMM: CTA 128x128, K-step 32, 3-stage (48KB).
// mode 0: Cf = acc (fp32)
// mode 2: g = sigmoid(acc + bias[n]); C16 = fp16(g * (Xh+Xl)[m][n])
// =================================================================================
#define HSTAGEB 16384
#define HSMEM   (3 * HSTAGEB)

__device__ __forceinline__ void load_stage_h(
    const __half* __restrict__ A, const __half* __restrict__ B,
    int K, int k0, int bm, int bn, uint32_t sstage, int tid)
{
#pragma unroll
    for (int it = 0; it < 4; it++) {
        int cidx = tid + it * 256;
        int t = cidx >> 9;
        int row = (cidx >> 2) & 127;
        int c = cidx & 3;
        const __half* src = t ? B : A;
        int rb = t ? bn : bm;
        const __half* gsrc = src + (size_t)(rb + row) * K + k0 + c * 8;
        uint32_t dst = sstage + t * 8192 + row * 64 + ((c ^ ((row >> 1) & 3)) << 4);
        CP_ASYNC16(dst, gsrc);
    }
    CP_COMMIT();
}

__global__ __launch_bounds__(256, 2) void gemm_fp16(
    const __half* __restrict__ A, const __half* __restrict__ B,
    int K, int mode,
    float* __restrict__ Cf, __half* __restrict__ C16,
    const float* __restrict__ bias,
    const __nv_bfloat16* __restrict__ Xh, const __nv_bfloat16* __restrict__ Xl,
    int ldc)
{
    extern __shared__ char smem[];
    const uint32_t sb = smem_u32(smem);
    const int tid = threadIdx.x;
    const int wid = tid >> 5, lane = tid & 31;
    const int bm = blockIdx.y * 128;
    const int bn = blockIdx.x * 128;
    const int wm = (wid >> 2) * 64;
    const int wn = (wid & 3) * 32;

    float acc[4][4][4];
#pragma unroll
    for (int mi = 0; mi < 4; mi++)
#pragma unroll
        for (int nj = 0; nj < 4; nj++)
#pragma unroll
            for (int q = 0; q < 4; q++) acc[mi][nj][q] = 0.f;

    const int nchunk = K >> 5;
    load_stage_h(A, B, K, 0, bm, bn, sb, tid);
    load_stage_h(A, B, K, 32, bm, bn, sb + HSTAGEB, tid);

    int slot = 0;
    for (int i = 0; i < nchunk; i++) {
        if (i + 1 < nchunk) CP_WAIT1(); else CP_WAIT0();
        __syncthreads();
        if (i + 2 < nchunk) {
            int ns = slot + 2; if (ns >= 3) ns -= 3;
            load_stage_h(A, B, K, (i + 2) << 5, bm, bn, sb + ns * HSTAGEB, tid);
        }

        const uint32_t st = sb + slot * HSTAGEB;
#pragma unroll
        for (int ks = 0; ks < 2; ks++) {
            uint32_t ah[4][4], bh[2][4];
#pragma unroll
            for (int mi = 0; mi < 4; mi++) {
                int row = wm + mi * 16 + (lane & 15);
                int ch = (lane >> 4) + ks * 2;
                uint32_t ad = st + row * 64 + ((ch ^ ((row >> 1) & 3)) << 4);
                LDSM4(ah[mi], ad);
            }
#pragma unroll
            for (int nb = 0; nb < 2; nb++) {
                int row = wn + nb * 16 + (lane & 7) + ((lane >> 4) << 3);
                int ch = ((lane >> 3) & 1) + ks * 2;
                uint32_t ad = st + 8192 + row * 64 + ((ch ^ ((row >> 1) & 3)) << 4);
                LDSM4(bh[nb], ad);
            }
#pragma unroll
            for (int mi = 0; mi < 4; mi++)
#pragma unroll
                for (int nj = 0; nj < 4; nj++) {
                    uint32_t* bhp = &bh[nj >> 1][(nj & 1) * 2];
                    MMAH(acc[mi][nj], ah[mi], bhp);
                }
        }
        if (++slot >= 3) slot = 0;
    }

    // epilogue
#pragma unroll
    for (int mi = 0; mi < 4; mi++) {
#pragma unroll
        for (int r = 0; r < 2; r++) {
            int m = bm + wm + mi * 16 + (lane >> 2) + r * 8;
#pragma unroll
            for (int nj = 0; nj < 4; nj++) {
                int n = bn + wn + nj * 8 + (lane & 3) * 2;
                float v0 = acc[mi][nj][r * 2 + 0];
                float v1 = acc[mi][nj][r * 2 + 1];
                size_t o = (size_t)m * ldc + n;
                if (mode == 0) {
                    *(float2*)(Cf + o) = make_float2(v0, v1);
                } else {
                    float g0 = 1.f / (1.f + __expf(-(v0 + bias[n])));
                    float g1 = 1.f / (1.f + __expf(-(v1 + bias[n + 1])));
                    float a0 = __bfloat162float(Xh[o]) + __bfloat162float(Xl[o]);
                    float a1 = __bfloat162float(Xh[o + 1]) + __bfloat162float(Xl[o + 1]);
                    *(__half2*)(C16 + o) = __floats2half2_rn(g0 * a0, g1 * a1);
                }
            }
        }
    }
}

// =================================================================================
// Flash attention, HMMA bf16 3-term split. All 4 directions via blockIdx.z.
// =================================================================================
#define ATTN_SMEM 65536

__global__ __launch_bounds__(128) void attn_kernel(
    const __nv_bfloat16* __restrict__ qkvh, const __nv_bfloat16* __restrict__ qkvl,
    __nv_bfloat16* __restrict__ attnh, __nv_bfloat16* __restrict__ attnl)
{
    extern __shared__ char smem[];
    const uint32_t sb = smem_u32(smem);
    const int dir = blockIdx.z;
    const int tr = dir >= 2, rev = dir & 1;
    qkvh += (size_t)dir * NTOK * 3072;
    qkvl += (size_t)dir * NTOK * 3072;
    attnh += (size_t)dir * NTOK * 1024;
    attnl += (size_t)dir * NTOK * 1024;
    const int qt = blockIdx.x;
    const int b  = blockIdx.y >> 4;
    const int h  = blockIdx.y & 15;
    const int tid = threadIdx.x;
    const int wid = tid >> 5, lane = tid & 31;
    const size_t bq = (size_t)b * TSEQ;
    const uint32_t sQh = sb, sQl = sb + 8192, sKh = sb + 16384, sKl = sb + 24576;
    const uint32_t sVh = sb + 32768, sVl = sb + 40960, sPh = sb + 49152, sPl = sb + 57344;

    {
        const __nv_bfloat162 s2 = __float2bfloat162_rn(0.125f);
        for (int i = tid; i < 1024; i += 128) {
            int half = i >> 9;
            int j = i & 511;
            int row = j >> 3, c = j & 7;
            int t = qt * 64 + row;
            int tok = tr ? ((t & 31) * 32 + (t >> 5)) : t;
            const __nv_bfloat16* src = (half ? qkvl : qkvh) + (bq + tok) * 3072 + h * 64 + c * 8;
            uint4 v = *(const uint4*)src;
            __nv_bfloat162* p2 = (__nv_bfloat162*)&v;
#pragma unroll
            for (int q = 0; q < 4; q++) p2[q] = __hmul2(p2[q], s2);
            uint32_t off = half * 8192 + row * 128 + ((c ^ (row & 7)) << 4);
            *(uint4*)(smem + off) = v;
        }
    }

    float m0[2] = {-1e30f, -1e30f}, l0[2] = {0.f, 0.f};
    float o[8][4];
#pragma unroll
    for (int nj = 0; nj < 8; nj++)
#pragma unroll
        for (int q = 0; q < 4; q++) o[nj][q] = 0.f;

    const int kt_lo = rev ? qt : 0;
    const int kt_hi = rev ? 15 : qt;

    for (int kt = kt_lo; kt <= kt_hi; kt++) {
        __syncthreads();
        for (int i = tid; i < 2048; i += 128) {
            int arr = i >> 9;
            int j = i & 511;
            int row = j >> 3, c = j & 7;
            int t = kt * 64 + row;
            int tok = tr ? ((t & 31) * 32 + (t >> 5)) : t;
            const __nv_bfloat16* src = ((arr & 1) ? qkvl : qkvh)
                + (bq + tok) * 3072 + 1024 + (arr >> 1) * 1024 + h * 64 + c * 8;
            uint32_t dst = sKh + arr * 8192 + row * 128 + ((c ^ (row & 7)) << 4);
            CP_ASYNC16(dst, src);
        }
        CP_COMMIT(); CP_WAIT0();
        __syncthreads();

        float s[8][4];
#pragma unroll
        for (int nj = 0; nj < 8; nj++)
#pragma unroll
            for (int q = 0; q < 4; q++) s[nj][q] = 0.f;
#pragma unroll
        for (int kk = 0; kk < 4; kk++) {
            uint32_t qh_f[4], ql_f[4];
            {
                int row = wid * 16 + (lane & 15);
                int ch = (lane >> 4) + kk * 2;
                uint32_t ad = row * 128 + ((ch ^ (row & 7)) << 4);
                LDSM4(qh_f, sQh + ad);
                LDSM4(ql_f, sQl + ad);
            }
#pragma unroll
            for (int nb = 0; nb < 4; nb++) {
                uint32_t kh_f[4], kl_f[4];
                int row = nb * 16 + (lane & 7) + ((lane >> 4) << 3);
                int ch = ((lane >> 3) & 1) + kk * 2;
                uint32_t ad = row * 128 + ((ch ^ (row & 7)) << 4);
                LDSM4(kh_f, sKh + ad);
                LDSM4(kl_f, sKl + ad);
#pragma unroll
                for (int half = 0; half < 2; half++) {
                    int nj = nb * 2 + half;
                    uint32_t* bhp = &kh_f[half * 2];
                    uint32_t* blp = &kl_f[half * 2];
                    MMA(s[nj], qh_f, bhp);
                    MMA(s[nj], qh_f, blp);
                    MMA(s[nj], ql_f, bhp);
                }
            }
        }

        if (kt == qt) {
#pragma unroll
            for (int nj = 0; nj < 8; nj++)
#pragma unroll
                for (int q = 0; q < 4; q++) {
                    int rr = q >> 1;
                    int qi = qt * 64 + wid * 16 + (lane >> 2) + rr * 8;
                    int ki = kt * 64 + nj * 8 + (lane & 3) * 2 + (q & 1);
                    bool valid = rev ? (ki >= qi) : (ki <= qi);
                    if (!valid) s[nj][q] = -1e30f;
                }
        }

#pragma unroll
        for (int rr = 0; rr < 2; rr++) {
            float vm = -1e30f;
#pragma unroll
            for (int nj = 0; nj < 8; nj++) {
                vm = fmaxf(vm, s[nj][rr * 2 + 0]);
                vm = fmaxf(vm, s[nj][rr * 2 + 1]);
            }
            vm = fmaxf(vm, __shfl_xor_sync(0xffffffffu, vm, 1));
            vm = fmaxf(vm, __shfl_xor_sync(0xffffffffu, vm, 2));
            float mn = fmaxf(m0[rr], vm);
            float fac = __expf(m0[rr] - mn);
            float rs = 0.f;
            int qrow = wid * 16 + (lane >> 2) + rr * 8;
#pragma unroll
            for (int nj = 0; nj < 8; nj++) {
                float p0 = __expf(s[nj][rr * 2 + 0] - mn);
                float p1 = __expf(s[nj][rr * 2 + 1] - mn);
                rs += p0 + p1;
                __nv_bfloat16 h0 = __float2bfloat16(p0);
                __nv_bfloat16 h1 = __float2bfloat16(p1);
                __nv_bfloat16 e0 = __float2bfloat16(p0 - __bfloat162float(h0));
                __nv_bfloat16 e1 = __float2bfloat16(p1 - __bfloat162float(h1));
                uint32_t off = qrow * 128 + ((nj ^ (qrow & 7)) << 4) + (lane & 3) * 4;
                __nv_bfloat162 hp; hp.x = h0; hp.y = h1;
                __nv_bfloat162 lp; lp.x = e0; lp.y = e1;
                *(__nv_bfloat162*)(smem + (sPh - sb) + off) = hp;
                *(__nv_bfloat162*)(smem + (sPl - sb) + off) = lp;
            }
            rs += __shfl_xor_sync(0xffffffffu, rs, 1);
            rs += __shfl_xor_sync(0xffffffffu, rs, 2);
            l0[rr] = l0[rr] * fac + rs;
            m0[rr] = mn;
#pragma unroll
            for (int nj = 0; nj < 8; nj++) {
                o[nj][rr * 2 + 0] *= fac;
                o[nj][rr * 2 + 1] *= fac;
            }
        }

#pragma unroll
        for (int kk = 0; kk < 4; kk++) {
            uint32_t ph_f[4], pl_f[4];
            {
                int row = wid * 16 + (lane & 15);
                int ch = (lane >> 4) + kk * 2;
                uint32_t ad = row * 128 + ((ch ^ (row & 7)) << 4);
                LDSM4(ph_f, sPh + ad);
                LDSM4(pl_f, sPl + ad);
            }
#pragma unroll
            for (int nb = 0; nb < 4; nb++) {
                uint32_t vh_f[4], vl_f[4];
                int row = kk * 16 + (lane & 15);
                int ch = (nb * 2 + (lane >> 4)) ^ (row & 7);
                uint32_t ad = row * 128 + (ch << 4);
                LDSM4T(vh_f, sVh + ad);
                LDSM4T(vl_f, sVl + ad);
#pragma unroll
                for (int half = 0; half < 2; half++) {
                    int nj = nb * 2 + half;
                    uint32_t* bhp = &vh_f[half * 2];
                    uint32_t* blp = &vl_f[half * 2];
                    MMA(o[nj], ph_f, bhp);
                    MMA(o[nj], ph_f, blp);
                    MMA(o[nj], pl_f, bhp);
                }
            }
        }
    }

#pragma unroll
    for (int rr = 0; rr < 2; rr++) {
        float inv = 1.f / l0[rr];
        int qrow = wid * 16 + (lane >> 2) + rr * 8;
        int t = qt * 64 + qrow;
        int tok = tr ? ((t & 31) * 32 + (t >> 5)) : t;
        size_t base = (bq + tok) * 1024 + h * 64;
#pragma unroll
        for (int nj = 0; nj < 8; nj++) {
            int d = nj * 8 + (lane & 3) * 2;
            float v0 = o[nj][rr * 2 + 0] * inv;
            float v1 = o[nj][rr * 2 + 1] * inv;
            __nv_bfloat16 h0 = __float2bfloat16(v0);
            __nv_bfloat16 h1 = __float2bfloat16(v1);
            __nv_bfloat16 e0 = __float2bfloat16(v0 - __bfloat162float(h0));
            __nv_bfloat16 e1 = __float2bfloat16(v1 - __bfloat162float(h1));
            __nv_bfloat162 hp; hp.x = h0; hp.y = h1;
            __nv_bfloat162 lp; lp.x = e0; lp.y = e1;
            *(__nv_bfloat162*)(attnh + base + d) = hp;
            *(__nv_bfloat162*)(attnl + base + d) = lp;
        }
    }
}

// =================================================================================
// RMSNorm epilogue
// =================================================================================
__global__ __launch_bounds__(256) void rmsnorm_kernel(
    const float* __restrict__ fused, const float* __restrict__ x,
    const float* __restrict__ w, float* __restrict__ out)
{
    const int t = blockIdx.x;
    const int tid = threadIdx.x;
    const float* fr = fused + (size_t)t * 1024;
    const float* xr = x + (size_t)t * 1024;
    float y[4];
    float ss = 0.f;
#pragma unroll
    for (int i = 0; i < 4; i++) {
        int c = tid + i * 256;
        y[i] = fr[c] + xr[c];
        ss += y[i] * y[i];
    }
#pragma unroll
    for (int off = 16; off >= 1; off >>= 1)
        ss += __shfl_xor_sync(0xffffffffu, ss, off);
    __shared__ float red[8];
    if ((tid & 31) == 0) red[tid >> 5] = ss;
    __syncthreads();
    float tot = red[0] + red[1] + red[2] + red[3] + red[4] + red[5] + red[6] + red[7];
    float r = rsqrtf(tot * (1.f / 1024.f) + 1e-6f);
    float* orow = out + (size_t)t * 1024;
#pragma unroll
    for (int i = 0; i < 4; i++) {
        int c = tid + i * 256;
        orow[c] = y[i] * r * w[c];
    }
}

// =================================================================================
// Launch
// =================================================================================
extern "C" void kernel_launch(void* const* d_in, const int* in_sizes, int n_in,
                              void* d_out, int out_size)
{
    const float* x       = (const float*)d_in[0];
    const float* w_qkv[4] = { (const float*)d_in[1], (const float*)d_in[3],
                              (const float*)d_in[5], (const float*)d_in[7] };
    const float* w_o[4]   = { (const float*)d_in[2], (const float*)d_in[4],
                              (const float*)d_in[6], (const float*)d_in[8] };
    const float* w_gate  = (const float*)d_in[9];
    const float* b_gate  = (const float*)d_in[10];
    const float* w_out   = (const float*)d_in[11];
    const float* norm_w  = (const float*)d_in[12];
    float* out = (float*)d_out;

    __nv_bfloat16 *xh, *xl, *wqkvh, *wqkvl, *woh, *wol;
    __nv_bfloat16 *qkvh, *qkvl, *attnh, *attnl, *conch, *concl;
    __half *wg16, *wout16, *conc16, *gat16;
    float *fused;
    cudaGetSymbolAddress((void**)&xh, g_xh);       cudaGetSymbolAddress((void**)&xl, g_xl);
    cudaGetSymbolAddress((void**)&wqkvh, g_wqkvh); cudaGetSymbolAddress((void**)&wqkvl, g_wqkvl);
    cudaGetSymbolAddress((void**)&woh, g_woh);     cudaGetSymbolAddress((void**)&wol, g_wol);
    cudaGetSymbolAddress((void**)&wg16, g_wg16);   cudaGetSymbolAddress((void**)&wout16, g_wout16);
    cudaGetSymbolAddress((void**)&qkvh, g_qkvh);   cudaGetSymbolAddress((void**)&qkvl, g_qkvl);
    cudaGetSymbolAddress((void**)&attnh, g_attnh); cudaGetSymbolAddress((void**)&attnl, g_attnl);
    cudaGetSymbolAddress((void**)&conch, g_conch); cudaGetSymbolAddress((void**)&concl, g_concl);
    cudaGetSymbolAddress((void**)&conc16, g_conc16); cudaGetSymbolAddress((void**)&gat16, g_gat16);
    cudaGetSymbolAddress((void**)&fused, g_fused);

    cudaFuncSetAttribute(attn_kernel, cudaFuncAttributeMaxDynamicSharedMemorySize, ATTN_SMEM);
    cudaFuncSetAttribute(gemm_bf16, cudaFuncAttributeMaxDynamicSharedMemorySize, GSMEM);
    cudaFuncSetAttribute(gemm_fp16, cudaFuncAttributeMaxDynamicSharedMemorySize, HSMEM);

    // converts
    convert_split<<<1024, 256>>>(x, xh, xl, NTOK * DMODEL);
    for (int d = 0; d < 4; d++) {
        convert_split<<<2048, 256>>>(w_qkv[d], wqkvh + (size_t)d * 3072 * 1024,
                                     wqkvl + (size_t)d * 3072 * 1024, 3072 * 1024);
        convert_split<<<1024, 256>>>(w_o[d], woh + (size_t)d * 1024 * 1024,
                                     wol + (size_t)d * 1024 * 1024, 1024 * 1024);
    }
    convert_fp16<<<4096, 256>>>(w_gate, wg16, 4096 * 4096);
    convert_fp16<<<2048, 256>>>(w_out, wout16, 1024 * 4096);

    // QKV for all 4 directions (bf16 3-term)
    for (int dir = 0; dir < 4; dir++) {
        gemm_bf16<<<dim3(3072 / 128, 4096 / 128), 256, GSMEM>>>(
            xh, xl, wqkvh + (size_t)dir * 3072 * 1024, wqkvl + (size_t)dir * 3072 * 1024,
            1024, 1,
            qkvh + (size_t)dir * NTOK * 3072, qkvl + (size_t)dir * NTOK * 3072,
            nullptr, 3072, 0, 0, 0, 0);
    }

    // attention, all directions in one launch
    attn_kernel<<<dim3(16, 4 * NH, 4), 128, ATTN_SMEM>>>(qkvh, qkvl, attnh, attnl);

    // O-proj, batched over directions; emit bf16 split + fp16 concat
    gemm_bf16<<<dim3(1024 / 128, 4096 / 128, 4), 256, GSMEM>>>(
        attnh, attnl, woh, wol,
        1024, 3, conch, concl, conc16,
        4096, 0, (size_t)NTOK * 1024, (size_t)1024 * 1024, 1024);

    // gate (fp16 1-term): sigmoid(conc16 @ wg16^T + b) * (conch+concl) -> gat16
    gemm_fp16<<<dim3(4096 / 128, 4096 / 128), 256, HSMEM>>>(
        conc16, wg16, 4096, 2, nullptr, gat16, b_gate, conch, concl, 4096);

    // out (fp16 1-term): gat16 @ wout16^T -> fused fp32
    gemm_fp16<<<dim3(1024 / 128, 4096 / 128), 256, HSMEM>>>(
        gat16, wout16, 4096, 0, fused, nullptr, nullptr, nullptr, nullptr, 1024);

    rmsnorm_kernel<<<NTOK, 256>>>(fused, x, norm_w, out);
}

// round 8
// speedup vs baseline: 4.5976x; 1.9199x over previous
#include <cuda_runtime.h>
#include <cuda_fp16.h>
#include <math.h>
#include <stdint.h>

#define NTOK 4096
#define DMODEL 1024
#define NH 16
#define TSEQ 1024

// ---------------- helpers ----------------
__device__ __forceinline__ uint32_t smem_u32(const void* p) {
    uint32_t a;
    asm("{ .reg .u64 t; cvta.to.shared.u64 t, %1; cvt.u32.u64 %0, t; }" : "=r"(a) : "l"(p));
    return a;
}

#define LDSM4(r, addr) \
    asm volatile("ldmatrix.sync.aligned.m8n8.x4.shared.b16 {%0,%1,%2,%3}, [%4];" \
        : "=r"((r)[0]), "=r"((r)[1]), "=r"((r)[2]), "=r"((r)[3]) : "r"(addr))

#define LDSM4T(r, addr) \
    asm volatile("ldmatrix.sync.aligned.m8n8.x4.trans.shared.b16 {%0,%1,%2,%3}, [%4];" \
        : "=r"((r)[0]), "=r"((r)[1]), "=r"((r)[2]), "=r"((r)[3]) : "r"(addr))

#define MMAH(c, a, b) \
    asm volatile("mma.sync.aligned.m16n8k16.row.col.f32.f16.f16.f32 " \
        "{%0,%1,%2,%3}, {%4,%5,%6,%7}, {%8,%9}, {%0,%1,%2,%3};" \
        : "+f"((c)[0]), "+f"((c)[1]), "+f"((c)[2]), "+f"((c)[3]) \
        : "r"((a)[0]), "r"((a)[1]), "r"((a)[2]), "r"((a)[3]), "r"((b)[0]), "r"((b)[1]))

#define CP_ASYNC16(dst, src) \
    asm volatile("cp.async.cg.shared.global [%0], [%1], 16;" :: "r"(dst), "l"(src) : "memory")
#define CP_COMMIT() asm volatile("cp.async.commit_group;" ::: "memory")
#define CP_WAIT0()  asm volatile("cp.async.wait_group 0;" ::: "memory")
#define CP_WAIT1()  asm volatile("cp.async.wait_group 1;" ::: "memory")

// ---------------- scratch (device globals) ----------------
__device__ __align__(256) __half g_x16[(size_t)NTOK * DMODEL];
__device__ __align__(256) __half g_wqkv16[(size_t)4 * 3072 * 1024];
__device__ __align__(256) __half g_wo16[(size_t)4 * 1024 * 1024];
__device__ __align__(256) __half g_wg16[(size_t)4096 * 4096];
__device__ __align__(256) __half g_wout16[(size_t)1024 * 4096];
__device__ __align__(256) __half g_qkv16[(size_t)4 * NTOK * 3072];
__device__ __align__(256) __half g_attn16[(size_t)4 * NTOK * 1024];
__device__ __align__(256) __half g_conc16[(size_t)NTOK * 4096];
__device__ __align__(256) __half g_gat16[(size_t)NTOK * 4096];
__device__ __align__(256) float g_fused[(size_t)NTOK * 1024];

// ---------------- fp32 -> fp16 (vectorized) ----------------
__global__ __launch_bounds__(256) void convert_fp16(
    const float* __restrict__ in, __half* __restrict__ o, int n)
{
    const int n4 = n >> 2;
    for (int i = blockIdx.x * 256 + threadIdx.x; i < n4; i += gridDim.x * 256) {
        float4 v = ((const float4*)in)[i];
        __half2 p[2];
        p[0] = __floats2half2_rn(v.x, v.y);
        p[1] = __floats2half2_rn(v.z, v.w);
        ((uint2*)o)[i] = *(uint2*)p;
    }
}

// =================================================================================
// HMMA fp16 single-term GEMM: CTA 128x128, K-step 32, 3-stage cp.async (48KB).
// C[m][coff+n] = sum_k A[m][k]*B[n][k]
// mode 0: Cf = acc (fp32)
// mode 1: C16 = fp16(acc)
// mode 2: g = sigmoid(acc + bias[n]); C16 = fp16(g * X16[m][n])
// Batched over blockIdx.z: A += z*sA, B += z*sB, C16 += z*sC, coff += z*sCoff.
// =================================================================================
#define HSTAGEB 16384
#define HSMEM   (3 * HSTAGEB)

__device__ __forceinline__ void load_stage_h(
    const __half* __restrict__ A, const __half* __restrict__ B,
    int K, int k0, int bm, int bn, uint32_t sstage, int tid)
{
#pragma unroll
    for (int it = 0; it < 4; it++) {
        int cidx = tid + it * 256;
        int t = cidx >> 9;
        int row = (cidx >> 2) & 127;
        int c = cidx & 3;
        const __half* src = t ? B : A;
        int rb = t ? bn : bm;
        const __half* gsrc = src + (size_t)(rb + row) * K + k0 + c * 8;
        uint32_t dst = sstage + t * 8192 + row * 64 + ((c ^ ((row >> 1) & 3)) << 4);
        CP_ASYNC16(dst, gsrc);
    }
    CP_COMMIT();
}

__global__ __launch_bounds__(256, 2) void gemm_fp16(
    const __half* __restrict__ A, const __half* __restrict__ B,
    int K, int mode,
    float* __restrict__ Cf, __half* __restrict__ C16,
    const float* __restrict__ bias, const __half* __restrict__ X16,
    int ldc, int coff, size_t sA, size_t sB, size_t sC, int sCoff)
{
    extern __shared__ char smem[];
    const uint32_t sb = smem_u32(smem);
    const int tid = threadIdx.x;
    const int wid = tid >> 5, lane = tid & 31;
    const int bm = blockIdx.y * 128;
    const int bn = blockIdx.x * 128;
    const int z = blockIdx.z;
    A += (size_t)z * sA; B += (size_t)z * sB;
    if (C16) C16 += (size_t)z * sC;
    coff += z * sCoff;
    const int wm = (wid >> 2) * 64;
    const int wn = (wid & 3) * 32;

    float acc[4][4][4];
#pragma unroll
    for (int mi = 0; mi < 4; mi++)
#pragma unroll
        for (int nj = 0; nj < 4; nj++)
#pragma unroll
            for (int q = 0; q < 4; q++) acc[mi][nj][q] = 0.f;

    const int nchunk = K >> 5;
    load_stage_h(A, B, K, 0, bm, bn, sb, tid);
    load_stage_h(A, B, K, 32, bm, bn, sb + HSTAGEB, tid);

    int slot = 0;
    for (int i = 0; i < nchunk; i++) {
        if (i + 1 < nchunk) CP_WAIT1(); else CP_WAIT0();
        __syncthreads();
        if (i + 2 < nchunk) {
            int ns = slot + 2; if (ns >= 3) ns -= 3;
            load_stage_h(A, B, K, (i + 2) << 5, bm, bn, sb + ns * HSTAGEB, tid);
        }

        const uint32_t st = sb + slot * HSTAGEB;
#pragma unroll
        for (int ks = 0; ks < 2; ks++) {
            uint32_t ah[4][4], bh[2][4];
#pragma unroll
            for (int mi = 0; mi < 4; mi++) {
                int row = wm + mi * 16 + (lane & 15);
                int ch = (lane >> 4) + ks * 2;
                uint32_t ad = st + row * 64 + ((ch ^ ((row >> 1) & 3)) << 4);
                LDSM4(ah[mi], ad);
            }
#pragma unroll
            for (int nb = 0; nb < 2; nb++) {
                int row = wn + nb * 16 + (lane & 7) + ((lane >> 4) << 3);
                int ch = ((lane >> 3) & 1) + ks * 2;
                uint32_t ad = st + 8192 + row * 64 + ((ch ^ ((row >> 1) & 3)) << 4);
                LDSM4(bh[nb], ad);
            }
#pragma unroll
            for (int mi = 0; mi < 4; mi++)
#pragma unroll
                for (int nj = 0; nj < 4; nj++) {
                    uint32_t* bhp = &bh[nj >> 1][(nj & 1) * 2];
                    MMAH(acc[mi][nj], ah[mi], bhp);
                }
        }
        if (++slot >= 3) slot = 0;
    }

    // epilogue
#pragma unroll
    for (int mi = 0; mi < 4; mi++) {
#pragma unroll
        for (int r = 0; r < 2; r++) {
            int m = bm + wm + mi * 16 + (lane >> 2) + r * 8;
#pragma unroll
            for (int nj = 0; nj < 4; nj++) {
                int n = bn + wn + nj * 8 + (lane & 3) * 2;
                float v0 = acc[mi][nj][r * 2 + 0];
                float v1 = acc[mi][nj][r * 2 + 1];
                size_t o = (size_t)m * ldc + coff + n;
                if (mode == 0) {
                    *(float2*)(Cf + o) = make_float2(v0, v1);
                } else if (mode == 1) {
                    *(__half2*)(C16 + o) = __floats2half2_rn(v0, v1);
                } else {
                    float g0 = 1.f / (1.f + __expf(-(v0 + bias[n])));
                    float g1 = 1.f / (1.f + __expf(-(v1 + bias[n + 1])));
                    float a0 = __half2float(X16[o]);
                    float a1 = __half2float(X16[o + 1]);
                    *(__half2*)(C16 + o) = __floats2half2_rn(g0 * a0, g1 * a1);
                }
            }
        }
    }
}

// =================================================================================
// Flash attention, HMMA fp16 single-term. All 4 directions via blockIdx.z.
// qkv16: [4][NTOK][3072] fp16; attn16: [4][NTOK][1024] fp16.
// Block: 128 threads (4 warps), one (b,h,qtile64). Smem: Q K V P, 8KB each = 32KB.
// =================================================================================
#define ATTN_SMEM 32768

__global__ __launch_bounds__(128) void attn_kernel(
    const __half* __restrict__ qkv16, __half* __restrict__ attn16)
{
    extern __shared__ char smem[];
    const uint32_t sb = smem_u32(smem);
    const int dir = blockIdx.z;
    const int tr = dir >= 2, rev = dir & 1;
    const __half* qkv = qkv16 + (size_t)dir * NTOK * 3072;
    __half* attn = attn16 + (size_t)dir * NTOK * 1024;
    const int qt = blockIdx.x;
    const int b  = blockIdx.y >> 4;
    const int h  = blockIdx.y & 15;
    const int tid = threadIdx.x;
    const int wid = tid >> 5, lane = tid & 31;
    const size_t bq = (size_t)b * TSEQ;
    const uint32_t sQ = sb, sK = sb + 8192, sV = sb + 16384, sP = sb + 24576;

    // ---- load Q (scaled by 1/8, permuted gather) ----
    {
        const __half2 s2 = __floats2half2_rn(0.125f, 0.125f);
        for (int i = tid; i < 512; i += 128) {
            int row = i >> 3, c = i & 7;
            int t = qt * 64 + row;
            int tok = tr ? ((t & 31) * 32 + (t >> 5)) : t;
            uint4 v = *(const uint4*)(qkv + (bq + tok) * 3072 + h * 64 + c * 8);
            __half2* p2 = (__half2*)&v;
#pragma unroll
            for (int q = 0; q < 4; q++) p2[q] = __hmul2(p2[q], s2);
            *(uint4*)(smem + row * 128 + ((c ^ (row & 7)) << 4)) = v;
        }
    }

    float m0[2] = {-1e30f, -1e30f}, l0[2] = {0.f, 0.f};
    float o[8][4];
#pragma unroll
    for (int nj = 0; nj < 8; nj++)
#pragma unroll
        for (int q = 0; q < 4; q++) o[nj][q] = 0.f;

    const int kt_lo = rev ? qt : 0;
    const int kt_hi = rev ? 15 : qt;

    for (int kt = kt_lo; kt <= kt_hi; kt++) {
        __syncthreads();
        // ---- load K,V via cp.async ----
        for (int i = tid; i < 1024; i += 128) {
            int arr = i >> 9;              // 0:K 1:V
            int j = i & 511;
            int row = j >> 3, c = j & 7;
            int t = kt * 64 + row;
            int tok = tr ? ((t & 31) * 32 + (t >> 5)) : t;
            const __half* src = qkv + (bq + tok) * 3072 + 1024 + arr * 1024 + h * 64 + c * 8;
            uint32_t dst = sK + arr * 8192 + row * 128 + ((c ^ (row & 7)) << 4);
            CP_ASYNC16(dst, src);
        }
        CP_COMMIT(); CP_WAIT0();
        __syncthreads();

        // ---- S = Q K^T ----
        float s[8][4];
#pragma unroll
        for (int nj = 0; nj < 8; nj++)
#pragma unroll
            for (int q = 0; q < 4; q++) s[nj][q] = 0.f;
#pragma unroll
        for (int kk = 0; kk < 4; kk++) {
            uint32_t q_f[4];
            {
                int row = wid * 16 + (lane & 15);
                int ch = (lane >> 4) + kk * 2;
                LDSM4(q_f, sQ + row * 128 + ((ch ^ (row & 7)) << 4));
            }
#pragma unroll
            for (int nb = 0; nb < 4; nb++) {
                uint32_t k_f[4];
                int row = nb * 16 + (lane & 7) + ((lane >> 4) << 3);
                int ch = ((lane >> 3) & 1) + kk * 2;
                LDSM4(k_f, sK + row * 128 + ((ch ^ (row & 7)) << 4));
#pragma unroll
                for (int half = 0; half < 2; half++)
                    MMAH(s[nb * 2 + half], q_f, (&k_f[half * 2]));
            }
        }

        // ---- mask (diagonal tile) ----
        if (kt == qt) {
#pragma unroll
            for (int nj = 0; nj < 8; nj++)
#pragma unroll
                for (int q = 0; q < 4; q++) {
                    int rr = q >> 1;
                    int qi = qt * 64 + wid * 16 + (lane >> 2) + rr * 8;
                    int ki = kt * 64 + nj * 8 + (lane & 3) * 2 + (q & 1);
                    bool valid = rev ? (ki >= qi) : (ki <= qi);
                    if (!valid) s[nj][q] = -1e30f;
                }
        }

        // ---- online softmax + P write (fp16) ----
#pragma unroll
        for (int rr = 0; rr < 2; rr++) {
            float vm = -1e30f;
#pragma unroll
            for (int nj = 0; nj < 8; nj++) {
                vm = fmaxf(vm, s[nj][rr * 2 + 0]);
                vm = fmaxf(vm, s[nj][rr * 2 + 1]);
            }
            vm = fmaxf(vm, __shfl_xor_sync(0xffffffffu, vm, 1));
            vm = fmaxf(vm, __shfl_xor_sync(0xffffffffu, vm, 2));
            float mn = fmaxf(m0[rr], vm);
            float fac = __expf(m0[rr] - mn);
            float rs = 0.f;
            int qrow = wid * 16 + (lane >> 2) + rr * 8;
#pragma unroll
            for (int nj = 0; nj < 8; nj++) {
                float p0 = __expf(s[nj][rr * 2 + 0] - mn);
                float p1 = __expf(s[nj][rr * 2 + 1] - mn);
                rs += p0 + p1;
                uint32_t off = qrow * 128 + ((nj ^ (qrow & 7)) << 4) + (lane & 3) * 4;
                *(__half2*)(smem + (sP - sb) + off) = __floats2half2_rn(p0, p1);
            }
            rs += __shfl_xor_sync(0xffffffffu, rs, 1);
            rs += __shfl_xor_sync(0xffffffffu, rs, 2);
            l0[rr] = l0[rr] * fac + rs;
            m0[rr] = mn;
#pragma unroll
            for (int nj = 0; nj < 8; nj++) {
                o[nj][rr * 2 + 0] *= fac;
                o[nj][rr * 2 + 1] *= fac;
            }
        }

        // ---- O += P V ----
#pragma unroll
        for (int kk = 0; kk < 4; kk++) {
            uint32_t p_f[4];
            {
                int row = wid * 16 + (lane & 15);
                int ch = (lane >> 4) + kk * 2;
                LDSM4(p_f, sP + row * 128 + ((ch ^ (row & 7)) << 4));
            }
#pragma unroll
            for (int nb = 0; nb < 4; nb++) {
                uint32_t v_f[4];
                int row = kk * 16 + (lane & 15);
                int ch = (nb * 2 + (lane >> 4)) ^ (row & 7);
                LDSM4T(v_f, sV + row * 128 + (ch << 4));
#pragma unroll
                for (int half = 0; half < 2; half++)
                    MMAH(o[nb * 2 + half], p_f, (&v_f[half * 2]));
            }
        }
    }

    // ---- normalize + permuted scatter (fp16) ----
#pragma unroll
    for (int rr = 0; rr < 2; rr++) {
        float inv = 1.f / l0[rr];
        int qrow = wid * 16 + (lane >> 2) + rr * 8;
        int t = qt * 64 + qrow;
        int tok = tr ? ((t & 31) * 32 + (t >> 5)) : t;
        size_t base = (bq + tok) * 1024 + h * 64;
#pragma unroll
        for (int nj = 0; nj < 8; nj++) {
            int d = nj * 8 + (lane & 3) * 2;
            *(__half2*)(attn + base + d) =
                __floats2half2_rn(o[nj][rr * 2 + 0] * inv, o[nj][rr * 2 + 1] * inv);
        }
    }
}

// =================================================================================
// RMSNorm epilogue
// =================================================================================
__global__ __launch_bounds__(256) void rmsnorm_kernel(
    const float* __restrict__ fused, const float* __restrict__ x,
    const float* __restrict__ w, float* __restrict__ out)
{
    const int t = blockIdx.x;
    const int tid = threadIdx.x;
    const float* fr = fused + (size_t)t * 1024;
    const float* xr = x + (size_t)t * 1024;
    float y[4];
    float ss = 0.f;
#pragma unroll
    for (int i = 0; i < 4; i++) {
        int c = tid + i * 256;
        y[i] = fr[c] + xr[c];
        ss += y[i] * y[i];
    }
#pragma unroll
    for (int off = 16; off >= 1; off >>= 1)
        ss += __shfl_xor_sync(0xffffffffu, ss, off);
    __shared__ float red[8];
    if ((tid & 31) == 0) red[tid >> 5] = ss;
    __syncthreads();
    float tot = red[0] + red[1] + red[2] + red[3] + red[4] + red[5] + red[6] + red[7];
    float r = rsqrtf(tot * (1.f / 1024.f) + 1e-6f);
    float* orow = out + (size_t)t * 1024;
#pragma unroll
    for (int i = 0; i < 4; i++) {
        int c = tid + i * 256;
        orow[c] = y[i] * r * w[c];
    }
}

// =================================================================================
// Launch
// =================================================================================
extern "C" void kernel_launch(void* const* d_in, const int* in_sizes, int n_in,
                              void* d_out, int out_size)
{
    const float* x       = (const float*)d_in[0];
    const float* w_qkv[4] = { (const float*)d_in[1], (const float*)d_in[3],
                              (const float*)d_in[5], (const float*)d_in[7] };
    const float* w_o[4]   = { (const float*)d_in[2], (const float*)d_in[4],
                              (const float*)d_in[6], (const float*)d_in[8] };
    const float* w_gate  = (const float*)d_in[9];
    const float* b_gate  = (const float*)d_in[10];
    const float* w_out   = (const float*)d_in[11];
    const float* norm_w  = (const float*)d_in[12];
    float* out = (float*)d_out;

    __half *x16, *wqkv16, *wo16, *wg16, *wout16, *qkv16, *attn16, *conc16, *gat16;
    float *fused;
    cudaGetSymbolAddress((void**)&x16, g_x16);
    cudaGetSymbolAddress((void**)&wqkv16, g_wqkv16);
    cudaGetSymbolAddress((void**)&wo16, g_wo16);
    cudaGetSymbolAddress((void**)&wg16, g_wg16);
    cudaGetSymbolAddress((void**)&wout16, g_wout16);
    cudaGetSymbolAddress((void**)&qkv16, g_qkv16);
    cudaGetSymbolAddress((void**)&attn16, g_attn16);
    cudaGetSymbolAddress((void**)&conc16, g_conc16);
    cudaGetSymbolAddress((void**)&gat16, g_gat16);
    cudaGetSymbolAddress((void**)&fused, g_fused);

    cudaFuncSetAttribute(attn_kernel, cudaFuncAttributeMaxDynamicSharedMemorySize, ATTN_SMEM);
    cudaFuncSetAttribute(gemm_fp16, cudaFuncAttributeMaxDynamicSharedMemorySize, HSMEM);

    // converts
    convert_fp16<<<1024, 256>>>(x, x16, NTOK * DMODEL);
    for (int d = 0; d < 4; d++) {
        convert_fp16<<<2048, 256>>>(w_qkv[d], wqkv16 + (size_t)d * 3072 * 1024, 3072 * 1024);
        convert_fp16<<<1024, 256>>>(w_o[d], wo16 + (size_t)d * 1024 * 1024, 1024 * 1024);
    }
    convert_fp16<<<4096, 256>>>(w_gate, wg16, 4096 * 4096);
    convert_fp16<<<2048, 256>>>(w_out, wout16, 1024 * 4096);

    // QKV, all 4 directions batched: x16 @ wqkv16[z]^T -> qkv16[z]
    gemm_fp16<<<dim3(3072 / 128, 4096 / 128, 4), 256, HSMEM>>>(
        x16, wqkv16, 1024, 1, nullptr, qkv16, nullptr, nullptr,
        3072, 0, 0, (size_t)3072 * 1024, (size_t)NTOK * 3072, 0);

    // attention, all directions in one launch
    attn_kernel<<<dim3(16, 4 * NH, 4), 128, ATTN_SMEM>>>(qkv16, attn16);

    // O-proj, batched: attn16[z] @ wo16[z]^T -> conc16[:, z*1024 + ...]
    gemm_fp16<<<dim3(1024 / 128, 4096 / 128, 4), 256, HSMEM>>>(
        attn16, wo16, 1024, 1, nullptr, conc16, nullptr, nullptr,
        4096, 0, (size_t)NTOK * 1024, (size_t)1024 * 1024, 0, 1024);

    // gate: sigmoid(conc16 @ wg16^T + b) * conc16 -> gat16
    gemm_fp16<<<dim3(4096 / 128, 4096 / 128), 256, HSMEM>>>(
        conc16, wg16, 4096, 2, nullptr, gat16, b_gate, conc16,
        4096, 0, 0, 0, 0, 0);

    // out: gat16 @ wout16^T -> fused fp32
    gemm_fp16<<<dim3(1024 / 128, 4096 / 128), 256, HSMEM>>>(
        gat16, wout16, 4096, 0, fused, nullptr, nullptr, nullptr,
        1024, 0, 0, 0, 0, 0);

    rmsnorm_kernel<<<NTOK, 256>>>(fused, x, norm_w, out);
}